// round 2
// baseline (speedup 1.0000x reference)
#include <cuda_runtime.h>
#include <cstdint>

#define N_NODES_MAX 50016
#define FEAT 256
#define MULC 64

// ---------------- scratch (static device globals; no allocs) ----------------
__device__ float g_xl[N_NODES_MAX * FEAT];    // fctp(x,z,W_l1) per node
__device__ float g_agg[N_NODES_MAX * FEAT];   // scatter-add target
// Packed weights:
// WA[((v*64+u)*16 + w4)*16 + m*4 + j],  m in {si0, si1, l10, l11}, w = w4*4+j
__device__ float g_WA[10 * 64 * 16 * 16];
// WC[((v*64+u)*16 + w4)*8 + m*4 + j],   m in {l20, l21}
__device__ float g_WC[10 * 64 * 16 * 8];

__device__ __forceinline__ void fma4(float* acc, float a, float4 w) {
    acc[0] += a * w.x; acc[1] += a * w.y; acc[2] += a * w.z; acc[3] += a * w.w;
}

__device__ __forceinline__ void red_add_v4(float* p, float4 v) {
    asm volatile("red.global.add.v4.f32 [%0], {%1,%2,%3,%4};"
                 :: "l"(p), "f"(v.x), "f"(v.y), "f"(v.z), "f"(v.w) : "memory");
}

// ---------------- weight prepack ----------------
__global__ void prepack_kernel(const float* __restrict__ si0, const float* __restrict__ si1,
                               const float* __restrict__ l10, const float* __restrict__ l11,
                               const float* __restrict__ l20, const float* __restrict__ l21) {
    int idx = blockIdx.x * blockDim.x + threadIdx.x;  // idx = u*640 + v*64 + w
    if (idx >= 64 * 10 * 64) return;
    int w = idx & 63;
    int v = (idx >> 6) % 10;
    int u = idx / 640;
    int w4 = w >> 2, j = w & 3;
    int baseA = ((v * 64 + u) * 16 + w4) * 16 + j;
    g_WA[baseA + 0]  = si0[idx];
    g_WA[baseA + 4]  = si1[idx];
    g_WA[baseA + 8]  = l10[idx];
    g_WA[baseA + 12] = l11[idx];
    int baseC = ((v * 64 + u) * 16 + w4) * 8 + j;
    g_WC[baseC + 0] = l20[idx];
    g_WC[baseC + 4] = l21[idx];
}

// ---------------- zero agg ----------------
__global__ void zero_agg_kernel(int n4) {
    float4* p = (float4*)g_agg;
    float4 z = make_float4(0.f, 0.f, 0.f, 0.f);
    for (int i = blockIdx.x * blockDim.x + threadIdx.x; i < n4; i += gridDim.x * blockDim.x)
        p[i] = z;
}

// ---------------- fctp dual: s -> out_s, xl -> g_xl ----------------
// Block: 32 nodes, all 64 outputs. Thread: 2 nodes x 4 channels x 4 w-cols x 2 outputs.
__global__ __launch_bounds__(256) void fctp_dual_kernel(
    const float* __restrict__ x, const float* __restrict__ z,
    float* __restrict__ out_s, int n)
{
    __shared__ float4 Xs[64 * 32];   // [u][local_node]: (c0, c1, c2, c3)
    __shared__ float zsh[32][11];

    const int t = threadIdx.x;
    const int nbase = blockIdx.x * 32;
    const int ng = t >> 4;       // 0..15 node group
    const int w4 = t & 15;       // 0..15 -> w = w4*4 + j
    const int ln0 = ng * 2;

    // Build Xs: Xs[u][ln] = {x0[u], x1[u][0], x1[u][1], x1[u][2]} for node nbase+ln
#pragma unroll
    for (int i = 0; i < 8; i++) {
        int f = t + i * 256;         // float4 index
        int u = f >> 5, ln = f & 31;
        int node = nbase + ln;
        float4 val = make_float4(0.f, 0.f, 0.f, 0.f);
        if (node < n) {
            const float* xr = x + (size_t)node * FEAT;
            val.x = xr[u];
            val.y = xr[64 + 3 * u];
            val.z = xr[64 + 3 * u + 1];
            val.w = xr[64 + 3 * u + 2];
        }
        Xs[f] = val;
    }
    for (int i = t; i < 320; i += 256) {
        int ln = i / 10, v = i % 10;
        int node = nbase + ln;
        zsh[ln][v] = (node < n) ? z[(size_t)node * 10 + v] : 0.f;
    }
    __syncthreads();

    float accS[32], accL[32];
#pragma unroll
    for (int i = 0; i < 32; i++) { accS[i] = 0.f; accL[i] = 0.f; }

    const float4* WA4 = (const float4*)g_WA;

    for (int v = 0; v < 10; v++) {
        const float zr0 = zsh[ln0][v];
        const float zr1 = zsh[ln0 + 1][v];
#pragma unroll 8
        for (int u = 0; u < 64; u++) {
            float4 xq0 = Xs[u * 32 + ln0];
            float4 xq1 = Xs[u * 32 + ln0 + 1];
            int wb = ((v * 64 + u) * 16 + w4) * 4;
            float4 wsi0 = WA4[wb + 0];
            float4 wsi1 = WA4[wb + 1];
            float4 wl10 = WA4[wb + 2];
            float4 wl11 = WA4[wb + 3];

            float a00 = xq0.x * zr0, a01 = xq0.y * zr0, a02 = xq0.z * zr0, a03 = xq0.w * zr0;
            float a10 = xq1.x * zr1, a11 = xq1.y * zr1, a12 = xq1.z * zr1, a13 = xq1.w * zr1;

            fma4(accS + 0,  a00, wsi0); fma4(accS + 4,  a01, wsi1);
            fma4(accS + 8,  a02, wsi1); fma4(accS + 12, a03, wsi1);
            fma4(accS + 16, a10, wsi0); fma4(accS + 20, a11, wsi1);
            fma4(accS + 24, a12, wsi1); fma4(accS + 28, a13, wsi1);

            fma4(accL + 0,  a00, wl10); fma4(accL + 4,  a01, wl11);
            fma4(accL + 8,  a02, wl11); fma4(accL + 12, a03, wl11);
            fma4(accL + 16, a10, wl10); fma4(accL + 20, a11, wl11);
            fma4(accL + 24, a12, wl11); fma4(accL + 28, a13, wl11);
        }
    }

    const float sc = 0.03952847075210474f;  // 1/sqrt(640)
#pragma unroll
    for (int nn = 0; nn < 2; nn++) {
        int node = nbase + ln0 + nn;
        if (node >= n) continue;
        float* os = out_s + (size_t)node * FEAT;
        float* ox = g_xl + (size_t)node * FEAT;
        const float* aS = accS + nn * 16;
        const float* aL = accL + nn * 16;
#pragma unroll
        for (int j = 0; j < 4; j++) {
            int w = w4 * 4 + j;
            os[w] = aS[j] * sc;
            ox[w] = aL[j] * sc;
#pragma unroll
            for (int c = 1; c < 4; c++) {
                os[64 + 3 * w + c - 1] = aS[c * 4 + j] * sc;
                ox[64 + 3 * w + c - 1] = aL[c * 4 + j] * sc;
            }
        }
    }
}

// ---------------- final fctp: out += fctp(agg, z, W_l2)/10 ----------------
__global__ __launch_bounds__(256) void fctp_final_kernel(
    const float* __restrict__ z, float* __restrict__ out, int n)
{
    __shared__ float4 Xs[64 * 32];
    __shared__ float zsh[32][11];

    const int t = threadIdx.x;
    const int nbase = blockIdx.x * 32;
    const int ng = t >> 4;
    const int w4 = t & 15;
    const int ln0 = ng * 2;

#pragma unroll
    for (int i = 0; i < 8; i++) {
        int f = t + i * 256;
        int u = f >> 5, ln = f & 31;
        int node = nbase + ln;
        float4 val = make_float4(0.f, 0.f, 0.f, 0.f);
        if (node < n) {
            const float* xr = g_agg + (size_t)node * FEAT;
            val.x = xr[u];
            val.y = xr[64 + 3 * u];
            val.z = xr[64 + 3 * u + 1];
            val.w = xr[64 + 3 * u + 2];
        }
        Xs[f] = val;
    }
    for (int i = t; i < 320; i += 256) {
        int ln = i / 10, v = i % 10;
        int node = nbase + ln;
        zsh[ln][v] = (node < n) ? z[(size_t)node * 10 + v] : 0.f;
    }
    __syncthreads();

    float acc[32];
#pragma unroll
    for (int i = 0; i < 32; i++) acc[i] = 0.f;

    const float4* WC4 = (const float4*)g_WC;

    for (int v = 0; v < 10; v++) {
        const float zr0 = zsh[ln0][v];
        const float zr1 = zsh[ln0 + 1][v];
#pragma unroll 8
        for (int u = 0; u < 64; u++) {
            float4 xq0 = Xs[u * 32 + ln0];
            float4 xq1 = Xs[u * 32 + ln0 + 1];
            int wb = ((v * 64 + u) * 16 + w4) * 2;
            float4 wl20 = WC4[wb + 0];
            float4 wl21 = WC4[wb + 1];

            float a00 = xq0.x * zr0, a01 = xq0.y * zr0, a02 = xq0.z * zr0, a03 = xq0.w * zr0;
            float a10 = xq1.x * zr1, a11 = xq1.y * zr1, a12 = xq1.z * zr1, a13 = xq1.w * zr1;

            fma4(acc + 0,  a00, wl20); fma4(acc + 4,  a01, wl21);
            fma4(acc + 8,  a02, wl21); fma4(acc + 12, a03, wl21);
            fma4(acc + 16, a10, wl20); fma4(acc + 20, a11, wl21);
            fma4(acc + 24, a12, wl21); fma4(acc + 28, a13, wl21);
        }
    }

    const float sc = 0.03952847075210474f * 0.1f;  // (1/sqrt(640)) / 10
#pragma unroll
    for (int nn = 0; nn < 2; nn++) {
        int node = nbase + ln0 + nn;
        if (node >= n) continue;
        float* os = out + (size_t)node * FEAT;
        const float* a = acc + nn * 16;
#pragma unroll
        for (int j = 0; j < 4; j++) {
            int w = w4 * 4 + j;
            os[w] += a[j] * sc;
#pragma unroll
            for (int c = 1; c < 4; c++) {
                os[64 + 3 * w + c - 1] += a[c * 4 + j] * sc;
            }
        }
    }
}

// ---------------- edge kernel: per-edge weight GEMM + TP + scatter-add ----------------
__global__ __launch_bounds__(256) void edge_kernel(
    const int* __restrict__ esrc, const int* __restrict__ edst,
    const float* __restrict__ elen, const float* __restrict__ eattr,
    const float* __restrict__ tpw, int n_edges)
{
    __shared__ float wbuf[8][256];
    __shared__ float xbuf[8][256];
    __shared__ float obuf[8][256];

    const int warp = threadIdx.x >> 5;
    const int lane = threadIdx.x & 31;
    const int e = blockIdx.x * 8 + warp;
    if (e >= n_edges) return;

    const int src = esrc[e];
    const int dst = edst[e];
    const float el = elen[(size_t)e * 32 + lane];
    const float4 at = ((const float4*)eattr)[e];  // (sh0, sh1x, sh1y, sh1z)

    // w = edge_len_emb @ tp_weight : lane computes cols [lane*8, lane*8+8)
    float acc[8];
#pragma unroll
    for (int i = 0; i < 8; i++) acc[i] = 0.f;
    const float4* tp4 = (const float4*)tpw;
#pragma unroll
    for (int d = 0; d < 32; d++) {
        float ed = __shfl_sync(0xffffffffu, el, d);
        float4 tA = tp4[d * 64 + lane * 2];
        float4 tB = tp4[d * 64 + lane * 2 + 1];
        acc[0] += ed * tA.x; acc[1] += ed * tA.y; acc[2] += ed * tA.z; acc[3] += ed * tA.w;
        acc[4] += ed * tB.x; acc[5] += ed * tB.y; acc[6] += ed * tB.z; acc[7] += ed * tB.w;
    }
    float4* wb4 = (float4*)wbuf[warp];
    wb4[lane * 2]     = make_float4(acc[0], acc[1], acc[2], acc[3]);
    wb4[lane * 2 + 1] = make_float4(acc[4], acc[5], acc[6], acc[7]);

    // gather x = xl[src]
    const float4* xr = (const float4*)(g_xl + (size_t)src * FEAT);
    float4* xb4 = (float4*)xbuf[warp];
    xb4[lane] = xr[lane];
    xb4[lane + 32] = xr[lane + 32];
    __syncwarp();

    const float ISQ2 = 0.7071067811865476f;
    const float ISQ3 = 0.5773502691896258f;
#pragma unroll
    for (int h = 0; h < 2; h++) {
        int u = lane + 32 * h;
        float x0  = xbuf[warp][u];
        float x10 = xbuf[warp][64 + 3 * u];
        float x11 = xbuf[warp][64 + 3 * u + 1];
        float x12 = xbuf[warp][64 + 3 * u + 2];
        float w1  = wbuf[warp][u];
        float w2v = wbuf[warp][64 + u];
        float w3  = wbuf[warp][128 + u];
        float w4v = wbuf[warp][192 + u];
        float dot = x10 * at.y + x11 * at.z + x12 * at.w;
        obuf[warp][u] = ISQ2 * (w1 * x0 * at.x + ISQ3 * w4v * dot);
        obuf[warp][64 + 3 * u]     = ISQ2 * (w2v * x0 * at.y + w3 * x10 * at.x);
        obuf[warp][64 + 3 * u + 1] = ISQ2 * (w2v * x0 * at.z + w3 * x11 * at.x);
        obuf[warp][64 + 3 * u + 2] = ISQ2 * (w2v * x0 * at.w + w3 * x12 * at.x);
    }
    __syncwarp();

    float* aggp = g_agg + (size_t)dst * FEAT;
    float4 r0 = ((float4*)obuf[warp])[lane];
    float4 r1 = ((float4*)obuf[warp])[lane + 32];
    red_add_v4(aggp + lane * 4, r0);
    red_add_v4(aggp + 128 + lane * 4, r1);
}

// ---------------- launch ----------------
extern "C" void kernel_launch(void* const* d_in, const int* in_sizes, int n_in,
                              void* d_out, int out_size) {
    const float* x     = (const float*)d_in[0];
    const float* z     = (const float*)d_in[1];
    const int*   esrc  = (const int*)d_in[2];
    const int*   edst  = (const int*)d_in[3];
    const float* elen  = (const float*)d_in[4];
    const float* eattr = (const float*)d_in[5];
    const float* Wsi0  = (const float*)d_in[6];
    const float* Wsi1  = (const float*)d_in[7];
    const float* Wl10  = (const float*)d_in[8];
    const float* Wl11  = (const float*)d_in[9];
    const float* Wl20  = (const float*)d_in[10];
    const float* Wl21  = (const float*)d_in[11];
    const float* tpw   = (const float*)d_in[12];
    float* out = (float*)d_out;

    const int n_nodes = in_sizes[0] / FEAT;
    const int n_edges = in_sizes[2];

    prepack_kernel<<<(64 * 10 * 64 + 255) / 256, 256>>>(Wsi0, Wsi1, Wl10, Wl11, Wl20, Wl21);

    const int nblocks = (n_nodes + 31) / 32;
    fctp_dual_kernel<<<nblocks, 256>>>(x, z, out, n_nodes);

    zero_agg_kernel<<<512, 256>>>(n_nodes * (FEAT / 4));

    edge_kernel<<<(n_edges + 7) / 8, 256>>>(esrc, edst, elen, eattr, tpw, n_edges);

    fctp_final_kernel<<<nblocks, 256>>>(z, out, n_nodes);
}

// round 3
// speedup vs baseline: 1.1562x; 1.1562x over previous
#include <cuda_runtime.h>
#include <cstdint>

#define N_NODES_MAX 50016
#define FEAT 256
#define MULC 64

// ---------------- scratch (static device globals; no allocs) ----------------
// QUAD layout: [node][u][4] = {x0[u], x1[u][0], x1[u][1], x1[u][2]}
__device__ float g_xl[N_NODES_MAX * FEAT];
__device__ float g_agg[N_NODES_MAX * FEAT];
// WA[((v*64+u)*16 + w4)*16 + m*4 + j],  m in {si0, si1, l10, l11}, w = w4*4+j
__device__ float g_WA[10 * 64 * 16 * 16];
// WC[((v*64+u)*16 + w4)*8 + m*4 + j],   m in {l20, l21}
__device__ float g_WC[10 * 64 * 16 * 8];
// Lane-exact packed tp weights: g_tpp[(d*32+lane)*8 + {w1,w2,w3,w4}@lane, {w1,w2,w3,w4}@lane+32]
__device__ float g_tpp[32 * 32 * 8];

__device__ __forceinline__ void fma4(float* acc, float a, float4 w) {
    acc[0] += a * w.x; acc[1] += a * w.y; acc[2] += a * w.z; acc[3] += a * w.w;
}

__device__ __forceinline__ void red_add_v4(float* p, float4 v) {
    asm volatile("red.global.add.v4.f32 [%0], {%1,%2,%3,%4};"
                 :: "l"(p), "f"(v.x), "f"(v.y), "f"(v.z), "f"(v.w) : "memory");
}

// ---------------- weight prepack ----------------
__global__ void prepack_kernel(const float* __restrict__ si0, const float* __restrict__ si1,
                               const float* __restrict__ l10, const float* __restrict__ l11,
                               const float* __restrict__ l20, const float* __restrict__ l21) {
    int idx = blockIdx.x * blockDim.x + threadIdx.x;  // idx = u*640 + v*64 + w
    if (idx >= 64 * 10 * 64) return;
    int w = idx & 63;
    int v = (idx >> 6) % 10;
    int u = idx / 640;
    int w4 = w >> 2, j = w & 3;
    int baseA = ((v * 64 + u) * 16 + w4) * 16 + j;
    g_WA[baseA + 0]  = si0[idx];
    g_WA[baseA + 4]  = si1[idx];
    g_WA[baseA + 8]  = l10[idx];
    g_WA[baseA + 12] = l11[idx];
    int baseC = ((v * 64 + u) * 16 + w4) * 8 + j;
    g_WC[baseC + 0] = l20[idx];
    g_WC[baseC + 4] = l21[idx];
}

__global__ void prepack_tp_kernel(const float* __restrict__ tpw) {
    int i = blockIdx.x * blockDim.x + threadIdx.x;  // i = d*32 + lane
    if (i >= 32 * 32) return;
    int d = i >> 5, lane = i & 31;
    const float* row = tpw + d * 256;
    float* o = g_tpp + i * 8;
    o[0] = row[lane];        o[1] = row[64 + lane];
    o[2] = row[128 + lane];  o[3] = row[192 + lane];
    o[4] = row[32 + lane];   o[5] = row[96 + lane];
    o[6] = row[160 + lane];  o[7] = row[224 + lane];
}

// ---------------- zero agg ----------------
__global__ void zero_agg_kernel(int n4) {
    float4* p = (float4*)g_agg;
    float4 z = make_float4(0.f, 0.f, 0.f, 0.f);
    for (int i = blockIdx.x * blockDim.x + threadIdx.x; i < n4; i += gridDim.x * blockDim.x)
        p[i] = z;
}

// ---------------- fctp dual: s -> out_s (orig layout), xl -> g_xl (quad layout) ----------------
__global__ __launch_bounds__(256) void fctp_dual_kernel(
    const float* __restrict__ x, const float* __restrict__ z,
    float* __restrict__ out_s, int n)
{
    __shared__ float4 Xs[64 * 32];   // [u][local_node]
    __shared__ float zsh[32][11];

    const int t = threadIdx.x;
    const int nbase = blockIdx.x * 32;
    const int ng = t >> 4;
    const int w4 = t & 15;
    const int ln0 = ng * 2;

#pragma unroll
    for (int i = 0; i < 8; i++) {
        int f = t + i * 256;
        int u = f >> 5, ln = f & 31;
        int node = nbase + ln;
        float4 val = make_float4(0.f, 0.f, 0.f, 0.f);
        if (node < n) {
            const float* xr = x + (size_t)node * FEAT;
            val.x = xr[u];
            val.y = xr[64 + 3 * u];
            val.z = xr[64 + 3 * u + 1];
            val.w = xr[64 + 3 * u + 2];
        }
        Xs[f] = val;
    }
    for (int i = t; i < 320; i += 256) {
        int ln = i / 10, v = i % 10;
        int node = nbase + ln;
        zsh[ln][v] = (node < n) ? z[(size_t)node * 10 + v] : 0.f;
    }
    __syncthreads();

    float accS[32], accL[32];
#pragma unroll
    for (int i = 0; i < 32; i++) { accS[i] = 0.f; accL[i] = 0.f; }

    const float4* WA4 = (const float4*)g_WA;

    for (int v = 0; v < 10; v++) {
        const float zr0 = zsh[ln0][v];
        const float zr1 = zsh[ln0 + 1][v];
#pragma unroll 8
        for (int u = 0; u < 64; u++) {
            float4 xq0 = Xs[u * 32 + ln0];
            float4 xq1 = Xs[u * 32 + ln0 + 1];
            int wb = ((v * 64 + u) * 16 + w4) * 4;
            float4 wsi0 = WA4[wb + 0];
            float4 wsi1 = WA4[wb + 1];
            float4 wl10 = WA4[wb + 2];
            float4 wl11 = WA4[wb + 3];

            float a00 = xq0.x * zr0, a01 = xq0.y * zr0, a02 = xq0.z * zr0, a03 = xq0.w * zr0;
            float a10 = xq1.x * zr1, a11 = xq1.y * zr1, a12 = xq1.z * zr1, a13 = xq1.w * zr1;

            fma4(accS + 0,  a00, wsi0); fma4(accS + 4,  a01, wsi1);
            fma4(accS + 8,  a02, wsi1); fma4(accS + 12, a03, wsi1);
            fma4(accS + 16, a10, wsi0); fma4(accS + 20, a11, wsi1);
            fma4(accS + 24, a12, wsi1); fma4(accS + 28, a13, wsi1);

            fma4(accL + 0,  a00, wl10); fma4(accL + 4,  a01, wl11);
            fma4(accL + 8,  a02, wl11); fma4(accL + 12, a03, wl11);
            fma4(accL + 16, a10, wl10); fma4(accL + 20, a11, wl11);
            fma4(accL + 24, a12, wl11); fma4(accL + 28, a13, wl11);
        }
    }

    const float sc = 0.03952847075210474f;  // 1/sqrt(640)
#pragma unroll
    for (int nn = 0; nn < 2; nn++) {
        int node = nbase + ln0 + nn;
        if (node >= n) continue;
        float* os = out_s + (size_t)node * FEAT;
        float4* ox4 = (float4*)(g_xl + (size_t)node * FEAT);
        const float* aS = accS + nn * 16;
        const float* aL = accL + nn * 16;
#pragma unroll
        for (int j = 0; j < 4; j++) {
            int w = w4 * 4 + j;
            os[w] = aS[j] * sc;
#pragma unroll
            for (int c = 1; c < 4; c++)
                os[64 + 3 * w + c - 1] = aS[c * 4 + j] * sc;
            // quad layout store for xl
            ox4[w] = make_float4(aL[j] * sc, aL[4 + j] * sc, aL[8 + j] * sc, aL[12 + j] * sc);
        }
    }
}

// ---------------- final fctp: out += fctp(agg(quad), z, W_l2)/10 ----------------
__global__ __launch_bounds__(256) void fctp_final_kernel(
    const float* __restrict__ z, float* __restrict__ out, int n)
{
    __shared__ float4 Xs[64 * 32];
    __shared__ float zsh[32][11];

    const int t = threadIdx.x;
    const int nbase = blockIdx.x * 32;
    const int ng = t >> 4;
    const int w4 = t & 15;
    const int ln0 = ng * 2;

    const float4* agg4 = (const float4*)g_agg;
#pragma unroll
    for (int i = 0; i < 8; i++) {
        int f = t + i * 256;
        int u = f >> 5, ln = f & 31;
        int node = nbase + ln;
        Xs[f] = (node < n) ? agg4[(size_t)node * 64 + u]
                           : make_float4(0.f, 0.f, 0.f, 0.f);
    }
    for (int i = t; i < 320; i += 256) {
        int ln = i / 10, v = i % 10;
        int node = nbase + ln;
        zsh[ln][v] = (node < n) ? z[(size_t)node * 10 + v] : 0.f;
    }
    __syncthreads();

    float acc[32];
#pragma unroll
    for (int i = 0; i < 32; i++) acc[i] = 0.f;

    const float4* WC4 = (const float4*)g_WC;

    for (int v = 0; v < 10; v++) {
        const float zr0 = zsh[ln0][v];
        const float zr1 = zsh[ln0 + 1][v];
#pragma unroll 8
        for (int u = 0; u < 64; u++) {
            float4 xq0 = Xs[u * 32 + ln0];
            float4 xq1 = Xs[u * 32 + ln0 + 1];
            int wb = ((v * 64 + u) * 16 + w4) * 2;
            float4 wl20 = WC4[wb + 0];
            float4 wl21 = WC4[wb + 1];

            float a00 = xq0.x * zr0, a01 = xq0.y * zr0, a02 = xq0.z * zr0, a03 = xq0.w * zr0;
            float a10 = xq1.x * zr1, a11 = xq1.y * zr1, a12 = xq1.z * zr1, a13 = xq1.w * zr1;

            fma4(acc + 0,  a00, wl20); fma4(acc + 4,  a01, wl21);
            fma4(acc + 8,  a02, wl21); fma4(acc + 12, a03, wl21);
            fma4(acc + 16, a10, wl20); fma4(acc + 20, a11, wl21);
            fma4(acc + 24, a12, wl21); fma4(acc + 28, a13, wl21);
        }
    }

    const float sc = 0.03952847075210474f * 0.1f;  // (1/sqrt(640)) / 10
#pragma unroll
    for (int nn = 0; nn < 2; nn++) {
        int node = nbase + ln0 + nn;
        if (node >= n) continue;
        float* os = out + (size_t)node * FEAT;
        const float* a = acc + nn * 16;
#pragma unroll
        for (int j = 0; j < 4; j++) {
            int w = w4 * 4 + j;
            os[w] += a[j] * sc;
#pragma unroll
            for (int c = 1; c < 4; c++)
                os[64 + 3 * w + c - 1] += a[c * 4 + j] * sc;
        }
    }
}

// ---------------- edge kernel: 4 edges/warp, no smem ----------------
#define EPW 4
__global__ __launch_bounds__(256) void edge_kernel(
    const int* __restrict__ esrc, const int* __restrict__ edst,
    const float* __restrict__ elen, const float* __restrict__ eattr,
    int n_edges)
{
    const int warp = threadIdx.x >> 5;
    const int lane = threadIdx.x & 31;
    const int ebase = (blockIdx.x * 8 + warp) * EPW;
    if (ebase >= n_edges) return;

    float el[EPW];
    int esafe[EPW];
    bool valid[EPW];
#pragma unroll
    for (int j = 0; j < EPW; j++) {
        int e = ebase + j;
        valid[j] = (e < n_edges);
        esafe[j] = valid[j] ? e : (n_edges - 1);
        el[j] = elen[(size_t)esafe[j] * 32 + lane];
    }

    // per-edge weight GEMM, lane-exact columns
    float acc[EPW * 8];
#pragma unroll
    for (int i = 0; i < EPW * 8; i++) acc[i] = 0.f;
    const float4* tpp4 = (const float4*)g_tpp;
#pragma unroll 8
    for (int d = 0; d < 32; d++) {
        float4 tA = tpp4[(d * 32 + lane) * 2];
        float4 tB = tpp4[(d * 32 + lane) * 2 + 1];
#pragma unroll
        for (int j = 0; j < EPW; j++) {
            float ed = __shfl_sync(0xffffffffu, el[j], d);
            fma4(acc + j * 8, ed, tA);
            fma4(acc + j * 8 + 4, ed, tB);
        }
    }

    const float ISQ2 = 0.7071067811865476f;
    const float ISQ3 = 0.5773502691896258f;

#pragma unroll
    for (int j = 0; j < EPW; j++) {
        if (!valid[j]) continue;
        int e = esafe[j];
        int src = esrc[e];
        int dst = edst[e];
        float4 at = ((const float4*)eattr)[e];  // (sh0, sh1x, sh1y, sh1z)

        const float4* xr = (const float4*)(g_xl + (size_t)src * FEAT);
        float* aggp = g_agg + (size_t)dst * FEAT;
#pragma unroll
        for (int h = 0; h < 2; h++) {
            float4 xq = xr[lane + 32 * h];     // {x0, x10, x11, x12}
            float w1  = acc[j * 8 + h * 4 + 0];
            float w2v = acc[j * 8 + h * 4 + 1];
            float w3  = acc[j * 8 + h * 4 + 2];
            float w4v = acc[j * 8 + h * 4 + 3];
            float dot = xq.y * at.y + xq.z * at.z + xq.w * at.w;
            float4 o;
            o.x = ISQ2 * (w1 * xq.x * at.x + ISQ3 * w4v * dot);
            o.y = ISQ2 * (w2v * xq.x * at.y + w3 * xq.y * at.x);
            o.z = ISQ2 * (w2v * xq.x * at.z + w3 * xq.z * at.x);
            o.w = ISQ2 * (w2v * xq.x * at.w + w3 * xq.w * at.x);
            red_add_v4(aggp + (lane + 32 * h) * 4, o);
        }
    }
}

// ---------------- launch ----------------
extern "C" void kernel_launch(void* const* d_in, const int* in_sizes, int n_in,
                              void* d_out, int out_size) {
    const float* x     = (const float*)d_in[0];
    const float* z     = (const float*)d_in[1];
    const int*   esrc  = (const int*)d_in[2];
    const int*   edst  = (const int*)d_in[3];
    const float* elen  = (const float*)d_in[4];
    const float* eattr = (const float*)d_in[5];
    const float* Wsi0  = (const float*)d_in[6];
    const float* Wsi1  = (const float*)d_in[7];
    const float* Wl10  = (const float*)d_in[8];
    const float* Wl11  = (const float*)d_in[9];
    const float* Wl20  = (const float*)d_in[10];
    const float* Wl21  = (const float*)d_in[11];
    const float* tpw   = (const float*)d_in[12];
    float* out = (float*)d_out;

    const int n_nodes = in_sizes[0] / FEAT;
    const int n_edges = in_sizes[2];

    prepack_kernel<<<(64 * 10 * 64 + 255) / 256, 256>>>(Wsi0, Wsi1, Wl10, Wl11, Wl20, Wl21);
    prepack_tp_kernel<<<4, 256>>>(tpw);

    const int nblocks = (n_nodes + 31) / 32;
    fctp_dual_kernel<<<nblocks, 256>>>(x, z, out, n_nodes);

    zero_agg_kernel<<<512, 256>>>(n_nodes * (FEAT / 4));

    const int edges_per_block = 8 * EPW;
    edge_kernel<<<(n_edges + edges_per_block - 1) / edges_per_block, 256>>>(
        esrc, edst, elen, eattr, n_edges);

    fctp_final_kernel<<<nblocks, 256>>>(z, out, n_nodes);
}

// round 5
// speedup vs baseline: 1.2436x; 1.0755x over previous
#include <cuda_runtime.h>
#include <cstdint>

#define N_NODES_MAX 50016
#define FEAT 256
#define MULC 64

typedef unsigned long long u64t;

// ---------------- scratch (static device globals; no allocs) ----------------
// QUAD layout: [node][u][4] = {x0[u], x1[u][0], x1[u][1], x1[u][2]}
__device__ float g_xl[N_NODES_MAX * FEAT];
__device__ float g_agg[N_NODES_MAX * FEAT];
// WA[((v*64+u)*16 + w4)*16 + m*4 + j],  m in {si0, si1, l10, l11}, w = w4*4+j
__device__ float g_WA[10 * 64 * 16 * 16];
// WC[((v*64+u)*16 + w4)*8 + m*4 + j],   m in {l20, l21}
__device__ float g_WC[10 * 64 * 16 * 8];
// Lane-exact packed tp weights
__device__ float g_tpp[32 * 32 * 8];

// ---------------- f32x2 packed-FMA helpers ----------------
__device__ __forceinline__ u64t pack2s(float a) {          // splat {a, a}
    u64t r;
    asm("mov.b64 %0, {%1, %1};" : "=l"(r) : "f"(a));
    return r;
}
__device__ __forceinline__ void unpack2(u64t v, float& a, float& b) {
    asm("mov.b64 {%0, %1}, %2;" : "=f"(a), "=f"(b) : "l"(v));
}
__device__ __forceinline__ void ffma2(u64t& d, u64t a, u64t b) {
    asm("fma.rn.f32x2 %0, %1, %2, %0;" : "+l"(d) : "l"(a), "l"(b));
}

__device__ __forceinline__ void red_add_v4(float* p, float4 v) {
    asm volatile("red.global.add.v4.f32 [%0], {%1,%2,%3,%4};"
                 :: "l"(p), "f"(v.x), "f"(v.y), "f"(v.z), "f"(v.w) : "memory");
}

// ---------------- weight prepack ----------------
__global__ void prepack_kernel(const float* __restrict__ si0, const float* __restrict__ si1,
                               const float* __restrict__ l10, const float* __restrict__ l11,
                               const float* __restrict__ l20, const float* __restrict__ l21) {
    int idx = blockIdx.x * blockDim.x + threadIdx.x;  // idx = u*640 + v*64 + w
    if (idx >= 64 * 10 * 64) return;
    int w = idx & 63;
    int v = (idx >> 6) % 10;
    int u = idx / 640;
    int w4 = w >> 2, j = w & 3;
    int baseA = ((v * 64 + u) * 16 + w4) * 16 + j;
    g_WA[baseA + 0]  = si0[idx];
    g_WA[baseA + 4]  = si1[idx];
    g_WA[baseA + 8]  = l10[idx];
    g_WA[baseA + 12] = l11[idx];
    int baseC = ((v * 64 + u) * 16 + w4) * 8 + j;
    g_WC[baseC + 0] = l20[idx];
    g_WC[baseC + 4] = l21[idx];
}

__global__ void prepack_tp_kernel(const float* __restrict__ tpw) {
    int i = blockIdx.x * blockDim.x + threadIdx.x;  // i = d*32 + lane
    if (i >= 32 * 32) return;
    int d = i >> 5, lane = i & 31;
    const float* row = tpw + d * 256;
    float* o = g_tpp + i * 8;
    o[0] = row[lane];        o[1] = row[64 + lane];
    o[2] = row[128 + lane];  o[3] = row[192 + lane];
    o[4] = row[32 + lane];   o[5] = row[96 + lane];
    o[6] = row[160 + lane];  o[7] = row[224 + lane];
}

// ---------------- zero agg ----------------
__global__ void zero_agg_kernel(int n4) {
    float4* p = (float4*)g_agg;
    float4 z = make_float4(0.f, 0.f, 0.f, 0.f);
    for (int i = blockIdx.x * blockDim.x + threadIdx.x; i < n4; i += gridDim.x * blockDim.x)
        p[i] = z;
}

// ---------------- fctp dual: s -> out_s (orig layout), xl -> g_xl (quad layout) ----------------
__global__ __launch_bounds__(256) void fctp_dual_kernel(
    const float* __restrict__ x, const float* __restrict__ z,
    float* __restrict__ out_s, int n)
{
    __shared__ float4 Xs[64 * 32];   // [u][local_node]
    __shared__ float zsh[32][11];

    const int t = threadIdx.x;
    const int nbase = blockIdx.x * 32;
    const int ng = t >> 4;
    const int w4 = t & 15;
    const int ln0 = ng * 2;

#pragma unroll
    for (int i = 0; i < 8; i++) {
        int f = t + i * 256;
        int u = f >> 5, ln = f & 31;
        int node = nbase + ln;
        float4 val = make_float4(0.f, 0.f, 0.f, 0.f);
        if (node < n) {
            const float* xr = x + (size_t)node * FEAT;
            val.x = xr[u];
            val.y = xr[64 + 3 * u];
            val.z = xr[64 + 3 * u + 1];
            val.w = xr[64 + 3 * u + 2];
        }
        Xs[f] = val;
    }
    for (int i = t; i < 320; i += 256) {
        int ln = i / 10, v = i % 10;
        int node = nbase + ln;
        zsh[ln][v] = (node < n) ? z[(size_t)node * 10 + v] : 0.f;
    }
    __syncthreads();

    u64t accS2[16], accL2[16];
#pragma unroll
    for (int i = 0; i < 16; i++) { accS2[i] = 0ull; accL2[i] = 0ull; }

    const ulonglong2* WA8 = (const ulonglong2*)g_WA;

    for (int v = 0; v < 10; v++) {
        const float zr0 = zsh[ln0][v];
        const float zr1 = zsh[ln0 + 1][v];
#pragma unroll 8
        for (int u = 0; u < 64; u++) {
            float4 xq0 = Xs[u * 32 + ln0];
            float4 xq1 = Xs[u * 32 + ln0 + 1];
            int wb = ((v * 64 + u) * 16 + w4) * 4;
            ulonglong2 wsi0 = WA8[wb + 0];
            ulonglong2 wsi1 = WA8[wb + 1];
            ulonglong2 wl10 = WA8[wb + 2];
            ulonglong2 wl11 = WA8[wb + 3];

            u64t a00 = pack2s(xq0.x * zr0), a01 = pack2s(xq0.y * zr0);
            u64t a02 = pack2s(xq0.z * zr0), a03 = pack2s(xq0.w * zr0);
            u64t a10 = pack2s(xq1.x * zr1), a11 = pack2s(xq1.y * zr1);
            u64t a12 = pack2s(xq1.z * zr1), a13 = pack2s(xq1.w * zr1);

            ffma2(accS2[0],  a00, wsi0.x); ffma2(accS2[1],  a00, wsi0.y);
            ffma2(accS2[2],  a01, wsi1.x); ffma2(accS2[3],  a01, wsi1.y);
            ffma2(accS2[4],  a02, wsi1.x); ffma2(accS2[5],  a02, wsi1.y);
            ffma2(accS2[6],  a03, wsi1.x); ffma2(accS2[7],  a03, wsi1.y);
            ffma2(accS2[8],  a10, wsi0.x); ffma2(accS2[9],  a10, wsi0.y);
            ffma2(accS2[10], a11, wsi1.x); ffma2(accS2[11], a11, wsi1.y);
            ffma2(accS2[12], a12, wsi1.x); ffma2(accS2[13], a12, wsi1.y);
            ffma2(accS2[14], a13, wsi1.x); ffma2(accS2[15], a13, wsi1.y);

            ffma2(accL2[0],  a00, wl10.x); ffma2(accL2[1],  a00, wl10.y);
            ffma2(accL2[2],  a01, wl11.x); ffma2(accL2[3],  a01, wl11.y);
            ffma2(accL2[4],  a02, wl11.x); ffma2(accL2[5],  a02, wl11.y);
            ffma2(accL2[6],  a03, wl11.x); ffma2(accL2[7],  a03, wl11.y);
            ffma2(accL2[8],  a10, wl10.x); ffma2(accL2[9],  a10, wl10.y);
            ffma2(accL2[10], a11, wl11.x); ffma2(accL2[11], a11, wl11.y);
            ffma2(accL2[12], a12, wl11.x); ffma2(accL2[13], a12, wl11.y);
            ffma2(accL2[14], a13, wl11.x); ffma2(accL2[15], a13, wl11.y);
        }
    }

    float accS[32], accL[32];
#pragma unroll
    for (int p = 0; p < 16; p++) {
        unpack2(accS2[p], accS[2 * p], accS[2 * p + 1]);
        unpack2(accL2[p], accL[2 * p], accL[2 * p + 1]);
    }

    const float sc = 0.03952847075210474f;  // 1/sqrt(640)
#pragma unroll
    for (int nn = 0; nn < 2; nn++) {
        int node = nbase + ln0 + nn;
        if (node >= n) continue;
        float* os = out_s + (size_t)node * FEAT;
        float4* ox4 = (float4*)(g_xl + (size_t)node * FEAT);
        const float* aS = accS + nn * 16;
        const float* aL = accL + nn * 16;
#pragma unroll
        for (int j = 0; j < 4; j++) {
            int w = w4 * 4 + j;
            os[w] = aS[j] * sc;
#pragma unroll
            for (int c = 1; c < 4; c++)
                os[64 + 3 * w + c - 1] = aS[c * 4 + j] * sc;
            ox4[w] = make_float4(aL[j] * sc, aL[4 + j] * sc, aL[8 + j] * sc, aL[12 + j] * sc);
        }
    }
}

// ---------------- final fctp: out += fctp(agg(quad), z, W_l2)/10 ----------------
__global__ __launch_bounds__(256) void fctp_final_kernel(
    const float* __restrict__ z, float* __restrict__ out, int n)
{
    __shared__ float4 Xs[64 * 32];
    __shared__ float zsh[32][11];

    const int t = threadIdx.x;
    const int nbase = blockIdx.x * 32;
    const int ng = t >> 4;
    const int w4 = t & 15;
    const int ln0 = ng * 2;

    const float4* agg4 = (const float4*)g_agg;
#pragma unroll
    for (int i = 0; i < 8; i++) {
        int f = t + i * 256;
        int u = f >> 5, ln = f & 31;
        int node = nbase + ln;
        Xs[f] = (node < n) ? agg4[(size_t)node * 64 + u]
                           : make_float4(0.f, 0.f, 0.f, 0.f);
    }
    for (int i = t; i < 320; i += 256) {
        int ln = i / 10, v = i % 10;
        int node = nbase + ln;
        zsh[ln][v] = (node < n) ? z[(size_t)node * 10 + v] : 0.f;
    }
    __syncthreads();

    u64t acc2[16];
#pragma unroll
    for (int i = 0; i < 16; i++) acc2[i] = 0ull;

    const ulonglong2* WC8 = (const ulonglong2*)g_WC;

    for (int v = 0; v < 10; v++) {
        const float zr0 = zsh[ln0][v];
        const float zr1 = zsh[ln0 + 1][v];
#pragma unroll 8
        for (int u = 0; u < 64; u++) {
            float4 xq0 = Xs[u * 32 + ln0];
            float4 xq1 = Xs[u * 32 + ln0 + 1];
            int wb = ((v * 64 + u) * 16 + w4) * 2;
            ulonglong2 wl20 = WC8[wb + 0];
            ulonglong2 wl21 = WC8[wb + 1];

            u64t a00 = pack2s(xq0.x * zr0), a01 = pack2s(xq0.y * zr0);
            u64t a02 = pack2s(xq0.z * zr0), a03 = pack2s(xq0.w * zr0);
            u64t a10 = pack2s(xq1.x * zr1), a11 = pack2s(xq1.y * zr1);
            u64t a12 = pack2s(xq1.z * zr1), a13 = pack2s(xq1.w * zr1);

            ffma2(acc2[0],  a00, wl20.x); ffma2(acc2[1],  a00, wl20.y);
            ffma2(acc2[2],  a01, wl21.x); ffma2(acc2[3],  a01, wl21.y);
            ffma2(acc2[4],  a02, wl21.x); ffma2(acc2[5],  a02, wl21.y);
            ffma2(acc2[6],  a03, wl21.x); ffma2(acc2[7],  a03, wl21.y);
            ffma2(acc2[8],  a10, wl20.x); ffma2(acc2[9],  a10, wl20.y);
            ffma2(acc2[10], a11, wl21.x); ffma2(acc2[11], a11, wl21.y);
            ffma2(acc2[12], a12, wl21.x); ffma2(acc2[13], a12, wl21.y);
            ffma2(acc2[14], a13, wl21.x); ffma2(acc2[15], a13, wl21.y);
        }
    }

    float acc[32];
#pragma unroll
    for (int p = 0; p < 16; p++) unpack2(acc2[p], acc[2 * p], acc[2 * p + 1]);

    const float sc = 0.03952847075210474f * 0.1f;  // (1/sqrt(640)) / 10
#pragma unroll
    for (int nn = 0; nn < 2; nn++) {
        int node = nbase + ln0 + nn;
        if (node >= n) continue;
        float* os = out + (size_t)node * FEAT;
        const float* a = acc + nn * 16;
#pragma unroll
        for (int j = 0; j < 4; j++) {
            int w = w4 * 4 + j;
            os[w] += a[j] * sc;
#pragma unroll
            for (int c = 1; c < 4; c++)
                os[64 + 3 * w + c - 1] += a[c * 4 + j] * sc;
        }
    }
}

// ---------------- edge kernel: 4 edges/warp, no smem, f32x2 GEMM ----------------
#define EPW 4
__global__ __launch_bounds__(256) void edge_kernel(
    const int* __restrict__ esrc, const int* __restrict__ edst,
    const float* __restrict__ elen, const float* __restrict__ eattr,
    int n_edges)
{
    const int warp = threadIdx.x >> 5;
    const int lane = threadIdx.x & 31;
    const int ebase = (blockIdx.x * 8 + warp) * EPW;
    if (ebase >= n_edges) return;

    float el[EPW];
    int esafe[EPW];
    bool valid[EPW];
#pragma unroll
    for (int j = 0; j < EPW; j++) {
        int e = ebase + j;
        valid[j] = (e < n_edges);
        esafe[j] = valid[j] ? e : (n_edges - 1);
        el[j] = elen[(size_t)esafe[j] * 32 + lane];
    }

    // per-edge weight GEMM, lane-exact columns, packed f32x2
    u64t acc2[EPW * 4];
#pragma unroll
    for (int i = 0; i < EPW * 4; i++) acc2[i] = 0ull;
    const ulonglong2* tpp8 = (const ulonglong2*)g_tpp;
#pragma unroll 8
    for (int d = 0; d < 32; d++) {
        ulonglong2 tA = tpp8[(d * 32 + lane) * 2];
        ulonglong2 tB = tpp8[(d * 32 + lane) * 2 + 1];
#pragma unroll
        for (int j = 0; j < EPW; j++) {
            u64t ed = pack2s(__shfl_sync(0xffffffffu, el[j], d));
            ffma2(acc2[j * 4 + 0], ed, tA.x);
            ffma2(acc2[j * 4 + 1], ed, tA.y);
            ffma2(acc2[j * 4 + 2], ed, tB.x);
            ffma2(acc2[j * 4 + 3], ed, tB.y);
        }
    }

    const float ISQ2 = 0.7071067811865476f;
    const float ISQ3 = 0.5773502691896258f;

#pragma unroll
    for (int j = 0; j < EPW; j++) {
        if (!valid[j]) continue;
        int e = esafe[j];
        int src = esrc[e];
        int dst = edst[e];
        float4 at = ((const float4*)eattr)[e];  // (sh0, sh1x, sh1y, sh1z)

        float wv[8];
        unpack2(acc2[j * 4 + 0], wv[0], wv[1]);
        unpack2(acc2[j * 4 + 1], wv[2], wv[3]);
        unpack2(acc2[j * 4 + 2], wv[4], wv[5]);
        unpack2(acc2[j * 4 + 3], wv[6], wv[7]);

        const float4* xr = (const float4*)(g_xl + (size_t)src * FEAT);
        float* aggp = g_agg + (size_t)dst * FEAT;
#pragma unroll
        for (int h = 0; h < 2; h++) {
            float4 xq = xr[lane + 32 * h];     // {x0, x10, x11, x12}
            float w1  = wv[h * 4 + 0];
            float w2v = wv[h * 4 + 1];
            float w3  = wv[h * 4 + 2];
            float w4v = wv[h * 4 + 3];
            float dot = xq.y * at.y + xq.z * at.z + xq.w * at.w;
            float4 o;
            o.x = ISQ2 * (w1 * xq.x * at.x + ISQ3 * w4v * dot);
            o.y = ISQ2 * (w2v * xq.x * at.y + w3 * xq.y * at.x);
            o.z = ISQ2 * (w2v * xq.x * at.z + w3 * xq.z * at.x);
            o.w = ISQ2 * (w2v * xq.x * at.w + w3 * xq.w * at.x);
            red_add_v4(aggp + (lane + 32 * h) * 4, o);
        }
    }
}

// ---------------- launch ----------------
extern "C" void kernel_launch(void* const* d_in, const int* in_sizes, int n_in,
                              void* d_out, int out_size) {
    const float* x     = (const float*)d_in[0];
    const float* z     = (const float*)d_in[1];
    const int*   esrc  = (const int*)d_in[2];
    const int*   edst  = (const int*)d_in[3];
    const float* elen  = (const float*)d_in[4];
    const float* eattr = (const float*)d_in[5];
    const float* Wsi0  = (const float*)d_in[6];
    const float* Wsi1  = (const float*)d_in[7];
    const float* Wl10  = (const float*)d_in[8];
    const float* Wl11  = (const float*)d_in[9];
    const float* Wl20  = (const float*)d_in[10];
    const float* Wl21  = (const float*)d_in[11];
    const float* tpw   = (const float*)d_in[12];
    float* out = (float*)d_out;

    const int n_nodes = in_sizes[0] / FEAT;
    const int n_edges = in_sizes[2];

    prepack_kernel<<<(64 * 10 * 64 + 255) / 256, 256>>>(Wsi0, Wsi1, Wl10, Wl11, Wl20, Wl21);
    prepack_tp_kernel<<<4, 256>>>(tpw);

    const int nblocks = (n_nodes + 31) / 32;
    fctp_dual_kernel<<<nblocks, 256>>>(x, z, out, n_nodes);

    zero_agg_kernel<<<512, 256>>>(n_nodes * (FEAT / 4));

    const int edges_per_block = 8 * EPW;
    edge_kernel<<<(n_edges + edges_per_block - 1) / edges_per_block, 256>>>(
        esrc, edst, elen, eattr, n_edges);

    fctp_final_kernel<<<nblocks, 256>>>(z, out, n_nodes);
}

// round 6
// speedup vs baseline: 1.8048x; 1.4513x over previous
#include <cuda_runtime.h>
#include <cstdint>

#define N_NODES_MAX 50016
#define FEAT 256
#define MULC 64

typedef unsigned long long u64t;

// ---------------- scratch (static device globals; no allocs) ----------------
// QUAD layout: [node][u][4] = {x0[u], x1[u][0], x1[u][1], x1[u][2]}
__device__ float g_xl[N_NODES_MAX * FEAT];
__device__ float g_agg[N_NODES_MAX * FEAT];
// Coalesced weight layout: g_WB[m][(v*64+u)*64 + w], m in {si0, si1, l10, l11}
__device__ float g_WB[4 * 640 * 64];
// g_WC2[m][(v*64+u)*64 + w], m in {l20, l21}
__device__ float g_WC2[2 * 640 * 64];
// Lane-exact packed tp weights, de-interleaved:
// g_tppA[(d*32+lane)*4 + {w1,w2,w3,w4}] for u=lane ; g_tppB for u=lane+32
__device__ float g_tppA[32 * 32 * 4];
__device__ float g_tppB[32 * 32 * 4];

// ---------------- f32x2 packed-FMA helpers ----------------
__device__ __forceinline__ u64t pack2s(float a) {          // splat {a, a}
    u64t r;
    asm("mov.b64 %0, {%1, %1};" : "=l"(r) : "f"(a));
    return r;
}
__device__ __forceinline__ void unpack2(u64t v, float& a, float& b) {
    asm("mov.b64 {%0, %1}, %2;" : "=f"(a), "=f"(b) : "l"(v));
}
__device__ __forceinline__ void ffma2(u64t& d, u64t a, u64t b) {
    asm("fma.rn.f32x2 %0, %1, %2, %0;" : "+l"(d) : "l"(a), "l"(b));
}

__device__ __forceinline__ void red_add_v4(float* p, float4 v) {
    asm volatile("red.global.add.v4.f32 [%0], {%1,%2,%3,%4};"
                 :: "l"(p), "f"(v.x), "f"(v.y), "f"(v.z), "f"(v.w) : "memory");
}

// ---------------- weight prepack ----------------
__global__ void prepack_kernel(const float* __restrict__ si0, const float* __restrict__ si1,
                               const float* __restrict__ l10, const float* __restrict__ l11,
                               const float* __restrict__ l20, const float* __restrict__ l21) {
    int idx = blockIdx.x * blockDim.x + threadIdx.x;  // idx = u*640 + v*64 + w
    if (idx >= 64 * 10 * 64) return;
    int w = idx & 63;
    int v = (idx >> 6) % 10;
    int u = idx / 640;
    int o = (v * 64 + u) * 64 + w;          // coalesced: w contiguous
    g_WB[o + 0 * 40960] = si0[idx];
    g_WB[o + 1 * 40960] = si1[idx];
    g_WB[o + 2 * 40960] = l10[idx];
    g_WB[o + 3 * 40960] = l11[idx];
    g_WC2[o + 0 * 40960] = l20[idx];
    g_WC2[o + 1 * 40960] = l21[idx];
}

__global__ void prepack_tp_kernel(const float* __restrict__ tpw) {
    int i = blockIdx.x * blockDim.x + threadIdx.x;  // i = d*32 + lane
    if (i >= 32 * 32) return;
    int d = i >> 5, lane = i & 31;
    const float* row = tpw + d * 256;
    float* a = g_tppA + i * 4;
    a[0] = row[lane];        a[1] = row[64 + lane];
    a[2] = row[128 + lane];  a[3] = row[192 + lane];
    float* b = g_tppB + i * 4;
    b[0] = row[32 + lane];   b[1] = row[96 + lane];
    b[2] = row[160 + lane];  b[3] = row[224 + lane];
}

// ---------------- zero agg ----------------
__global__ void zero_agg_kernel(int n4) {
    float4* p = (float4*)g_agg;
    float4 z = make_float4(0.f, 0.f, 0.f, 0.f);
    for (int i = blockIdx.x * blockDim.x + threadIdx.x; i < n4; i += gridDim.x * blockDim.x)
        p[i] = z;
}

// ---------------- fctp dual: s -> out_s (orig layout), xl -> g_xl (quad layout) ----------------
__global__ __launch_bounds__(256) void fctp_dual_kernel(
    const float* __restrict__ x, const float* __restrict__ z,
    float* __restrict__ out_s, int n)
{
    __shared__ float4 Xs[64 * 32];   // [u][local_node]
    __shared__ float zsh[32][11];

    const int t = threadIdx.x;
    const int nbase = blockIdx.x * 32;
    const int ng = t >> 4;
    const int w4 = t & 15;
    const int ln0 = ng * 2;

#pragma unroll
    for (int i = 0; i < 8; i++) {
        int f = t + i * 256;
        int u = f >> 5, ln = f & 31;
        int node = nbase + ln;
        float4 val = make_float4(0.f, 0.f, 0.f, 0.f);
        if (node < n) {
            const float* xr = x + (size_t)node * FEAT;
            val.x = xr[u];
            val.y = xr[64 + 3 * u];
            val.z = xr[64 + 3 * u + 1];
            val.w = xr[64 + 3 * u + 2];
        }
        Xs[f] = val;
    }
    for (int i = t; i < 320; i += 256) {
        int ln = i / 10, v = i % 10;
        int node = nbase + ln;
        zsh[ln][v] = (node < n) ? z[(size_t)node * 10 + v] : 0.f;
    }
    __syncthreads();

    u64t accS2[16], accL2[16];
#pragma unroll
    for (int i = 0; i < 16; i++) { accS2[i] = 0ull; accL2[i] = 0ull; }

    const ulonglong2* WB8 = (const ulonglong2*)g_WB;   // m stride = 10240 (u64x2 units)

    for (int v = 0; v < 10; v++) {
        const float zr0 = zsh[ln0][v];
        const float zr1 = zsh[ln0 + 1][v];
#pragma unroll 8
        for (int u = 0; u < 64; u++) {
            float4 xq0 = Xs[u * 32 + ln0];
            float4 xq1 = Xs[u * 32 + ln0 + 1];
            int base = (v * 64 + u) * 16 + w4;     // lanes contiguous in w4
            ulonglong2 wsi0 = WB8[base];
            ulonglong2 wsi1 = WB8[base + 10240];
            ulonglong2 wl10 = WB8[base + 20480];
            ulonglong2 wl11 = WB8[base + 30720];

            u64t a00 = pack2s(xq0.x * zr0), a01 = pack2s(xq0.y * zr0);
            u64t a02 = pack2s(xq0.z * zr0), a03 = pack2s(xq0.w * zr0);
            u64t a10 = pack2s(xq1.x * zr1), a11 = pack2s(xq1.y * zr1);
            u64t a12 = pack2s(xq1.z * zr1), a13 = pack2s(xq1.w * zr1);

            ffma2(accS2[0],  a00, wsi0.x); ffma2(accS2[1],  a00, wsi0.y);
            ffma2(accS2[2],  a01, wsi1.x); ffma2(accS2[3],  a01, wsi1.y);
            ffma2(accS2[4],  a02, wsi1.x); ffma2(accS2[5],  a02, wsi1.y);
            ffma2(accS2[6],  a03, wsi1.x); ffma2(accS2[7],  a03, wsi1.y);
            ffma2(accS2[8],  a10, wsi0.x); ffma2(accS2[9],  a10, wsi0.y);
            ffma2(accS2[10], a11, wsi1.x); ffma2(accS2[11], a11, wsi1.y);
            ffma2(accS2[12], a12, wsi1.x); ffma2(accS2[13], a12, wsi1.y);
            ffma2(accS2[14], a13, wsi1.x); ffma2(accS2[15], a13, wsi1.y);

            ffma2(accL2[0],  a00, wl10.x); ffma2(accL2[1],  a00, wl10.y);
            ffma2(accL2[2],  a01, wl11.x); ffma2(accL2[3],  a01, wl11.y);
            ffma2(accL2[4],  a02, wl11.x); ffma2(accL2[5],  a02, wl11.y);
            ffma2(accL2[6],  a03, wl11.x); ffma2(accL2[7],  a03, wl11.y);
            ffma2(accL2[8],  a10, wl10.x); ffma2(accL2[9],  a10, wl10.y);
            ffma2(accL2[10], a11, wl11.x); ffma2(accL2[11], a11, wl11.y);
            ffma2(accL2[12], a12, wl11.x); ffma2(accL2[13], a12, wl11.y);
            ffma2(accL2[14], a13, wl11.x); ffma2(accL2[15], a13, wl11.y);
        }
    }

    float accS[32], accL[32];
#pragma unroll
    for (int p = 0; p < 16; p++) {
        unpack2(accS2[p], accS[2 * p], accS[2 * p + 1]);
        unpack2(accL2[p], accL[2 * p], accL[2 * p + 1]);
    }

    const float sc = 0.03952847075210474f;  // 1/sqrt(640)
#pragma unroll
    for (int nn = 0; nn < 2; nn++) {
        int node = nbase + ln0 + nn;
        if (node >= n) continue;
        float* os = out_s + (size_t)node * FEAT;
        float4* ox4 = (float4*)(g_xl + (size_t)node * FEAT);
        const float* aS = accS + nn * 16;
        const float* aL = accL + nn * 16;
#pragma unroll
        for (int j = 0; j < 4; j++) {
            int w = w4 * 4 + j;
            os[w] = aS[j] * sc;
#pragma unroll
            for (int c = 1; c < 4; c++)
                os[64 + 3 * w + c - 1] = aS[c * 4 + j] * sc;
            ox4[w] = make_float4(aL[j] * sc, aL[4 + j] * sc, aL[8 + j] * sc, aL[12 + j] * sc);
        }
    }
}

// ---------------- final fctp: out += fctp(agg(quad), z, W_l2)/10 ----------------
__global__ __launch_bounds__(256) void fctp_final_kernel(
    const float* __restrict__ z, float* __restrict__ out, int n)
{
    __shared__ float4 Xs[64 * 32];
    __shared__ float zsh[32][11];

    const int t = threadIdx.x;
    const int nbase = blockIdx.x * 32;
    const int ng = t >> 4;
    const int w4 = t & 15;
    const int ln0 = ng * 2;

    const float4* agg4 = (const float4*)g_agg;
#pragma unroll
    for (int i = 0; i < 8; i++) {
        int f = t + i * 256;
        int u = f >> 5, ln = f & 31;
        int node = nbase + ln;
        Xs[f] = (node < n) ? agg4[(size_t)node * 64 + u]
                           : make_float4(0.f, 0.f, 0.f, 0.f);
    }
    for (int i = t; i < 320; i += 256) {
        int ln = i / 10, v = i % 10;
        int node = nbase + ln;
        zsh[ln][v] = (node < n) ? z[(size_t)node * 10 + v] : 0.f;
    }
    __syncthreads();

    u64t acc2[16];
#pragma unroll
    for (int i = 0; i < 16; i++) acc2[i] = 0ull;

    const ulonglong2* WC8 = (const ulonglong2*)g_WC2;

    for (int v = 0; v < 10; v++) {
        const float zr0 = zsh[ln0][v];
        const float zr1 = zsh[ln0 + 1][v];
#pragma unroll 8
        for (int u = 0; u < 64; u++) {
            float4 xq0 = Xs[u * 32 + ln0];
            float4 xq1 = Xs[u * 32 + ln0 + 1];
            int base = (v * 64 + u) * 16 + w4;
            ulonglong2 wl20 = WC8[base];
            ulonglong2 wl21 = WC8[base + 10240];

            u64t a00 = pack2s(xq0.x * zr0), a01 = pack2s(xq0.y * zr0);
            u64t a02 = pack2s(xq0.z * zr0), a03 = pack2s(xq0.w * zr0);
            u64t a10 = pack2s(xq1.x * zr1), a11 = pack2s(xq1.y * zr1);
            u64t a12 = pack2s(xq1.z * zr1), a13 = pack2s(xq1.w * zr1);

            ffma2(acc2[0],  a00, wl20.x); ffma2(acc2[1],  a00, wl20.y);
            ffma2(acc2[2],  a01, wl21.x); ffma2(acc2[3],  a01, wl21.y);
            ffma2(acc2[4],  a02, wl21.x); ffma2(acc2[5],  a02, wl21.y);
            ffma2(acc2[6],  a03, wl21.x); ffma2(acc2[7],  a03, wl21.y);
            ffma2(acc2[8],  a10, wl20.x); ffma2(acc2[9],  a10, wl20.y);
            ffma2(acc2[10], a11, wl21.x); ffma2(acc2[11], a11, wl21.y);
            ffma2(acc2[12], a12, wl21.x); ffma2(acc2[13], a12, wl21.y);
            ffma2(acc2[14], a13, wl21.x); ffma2(acc2[15], a13, wl21.y);
        }
    }

    float acc[32];
#pragma unroll
    for (int p = 0; p < 16; p++) unpack2(acc2[p], acc[2 * p], acc[2 * p + 1]);

    const float sc = 0.03952847075210474f * 0.1f;  // (1/sqrt(640)) / 10
#pragma unroll
    for (int nn = 0; nn < 2; nn++) {
        int node = nbase + ln0 + nn;
        if (node >= n) continue;
        float* os = out + (size_t)node * FEAT;
        const float* a = acc + nn * 16;
#pragma unroll
        for (int j = 0; j < 4; j++) {
            int w = w4 * 4 + j;
            os[w] += a[j] * sc;
#pragma unroll
            for (int c = 1; c < 4; c++)
                os[64 + 3 * w + c - 1] += a[c * 4 + j] * sc;
        }
    }
}

// ---------------- edge kernel: 4 edges/warp, no smem, f32x2 GEMM ----------------
#define EPW 4
__global__ __launch_bounds__(256) void edge_kernel(
    const int* __restrict__ esrc, const int* __restrict__ edst,
    const float* __restrict__ elen, const float* __restrict__ eattr,
    int n_edges)
{
    const int warp = threadIdx.x >> 5;
    const int lane = threadIdx.x & 31;
    const int ebase = (blockIdx.x * 8 + warp) * EPW;
    if (ebase >= n_edges) return;

    float el[EPW];
    int esafe[EPW];
    bool valid[EPW];
#pragma unroll
    for (int j = 0; j < EPW; j++) {
        int e = ebase + j;
        valid[j] = (e < n_edges);
        esafe[j] = valid[j] ? e : (n_edges - 1);
        el[j] = elen[(size_t)esafe[j] * 32 + lane];
    }

    // per-edge weight GEMM, lane-exact columns, packed f32x2
    u64t acc2[EPW * 4];
#pragma unroll
    for (int i = 0; i < EPW * 4; i++) acc2[i] = 0ull;
    const ulonglong2* tpA8 = (const ulonglong2*)g_tppA;
    const ulonglong2* tpB8 = (const ulonglong2*)g_tppB;
#pragma unroll 8
    for (int d = 0; d < 32; d++) {
        ulonglong2 tA = tpA8[d * 32 + lane];
        ulonglong2 tB = tpB8[d * 32 + lane];
#pragma unroll
        for (int j = 0; j < EPW; j++) {
            u64t ed = pack2s(__shfl_sync(0xffffffffu, el[j], d));
            ffma2(acc2[j * 4 + 0], ed, tA.x);
            ffma2(acc2[j * 4 + 1], ed, tA.y);
            ffma2(acc2[j * 4 + 2], ed, tB.x);
            ffma2(acc2[j * 4 + 3], ed, tB.y);
        }
    }

    const float ISQ2 = 0.7071067811865476f;
    const float ISQ3 = 0.5773502691896258f;

#pragma unroll
    for (int j = 0; j < EPW; j++) {
        if (!valid[j]) continue;
        int e = esafe[j];
        int src = esrc[e];
        int dst = edst[e];
        float4 at = ((const float4*)eattr)[e];  // (sh0, sh1x, sh1y, sh1z)

        float wv[8];
        unpack2(acc2[j * 4 + 0], wv[0], wv[1]);
        unpack2(acc2[j * 4 + 1], wv[2], wv[3]);
        unpack2(acc2[j * 4 + 2], wv[4], wv[5]);
        unpack2(acc2[j * 4 + 3], wv[6], wv[7]);

        const float4* xr = (const float4*)(g_xl + (size_t)src * FEAT);
        float* aggp = g_agg + (size_t)dst * FEAT;
#pragma unroll
        for (int h = 0; h < 2; h++) {
            float4 xq = xr[lane + 32 * h];     // {x0, x10, x11, x12}
            float w1  = wv[h * 4 + 0];
            float w2v = wv[h * 4 + 1];
            float w3  = wv[h * 4 + 2];
            float w4v = wv[h * 4 + 3];
            float dot = xq.y * at.y + xq.z * at.z + xq.w * at.w;
            float4 o;
            o.x = ISQ2 * (w1 * xq.x * at.x + ISQ3 * w4v * dot);
            o.y = ISQ2 * (w2v * xq.x * at.y + w3 * xq.y * at.x);
            o.z = ISQ2 * (w2v * xq.x * at.z + w3 * xq.z * at.x);
            o.w = ISQ2 * (w2v * xq.x * at.w + w3 * xq.w * at.x);
            red_add_v4(aggp + (lane + 32 * h) * 4, o);
        }
    }
}

// ---------------- launch ----------------
extern "C" void kernel_launch(void* const* d_in, const int* in_sizes, int n_in,
                              void* d_out, int out_size) {
    const float* x     = (const float*)d_in[0];
    const float* z     = (const float*)d_in[1];
    const int*   esrc  = (const int*)d_in[2];
    const int*   edst  = (const int*)d_in[3];
    const float* elen  = (const float*)d_in[4];
    const float* eattr = (const float*)d_in[5];
    const float* Wsi0  = (const float*)d_in[6];
    const float* Wsi1  = (const float*)d_in[7];
    const float* Wl10  = (const float*)d_in[8];
    const float* Wl11  = (const float*)d_in[9];
    const float* Wl20  = (const float*)d_in[10];
    const float* Wl21  = (const float*)d_in[11];
    const float* tpw   = (const float*)d_in[12];
    float* out = (float*)d_out;

    const int n_nodes = in_sizes[0] / FEAT;
    const int n_edges = in_sizes[2];

    prepack_kernel<<<(64 * 10 * 64 + 255) / 256, 256>>>(Wsi0, Wsi1, Wl10, Wl11, Wl20, Wl21);
    prepack_tp_kernel<<<4, 256>>>(tpw);
    zero_agg_kernel<<<512, 256>>>(n_nodes * (FEAT / 4));

    const int nblocks = (n_nodes + 31) / 32;
    fctp_dual_kernel<<<nblocks, 256>>>(x, z, out, n_nodes);

    const int edges_per_block = 8 * EPW;
    edge_kernel<<<(n_edges + edges_per_block - 1) / edges_per_block, 256>>>(
        esrc, edst, elen, eattr, n_edges);

    fctp_final_kernel<<<nblocks, 256>>>(z, out, n_nodes);
}

// round 7
// speedup vs baseline: 2.1971x; 1.2174x over previous
#include <cuda_runtime.h>
#include <cstdint>

#define N_NODES_MAX 50016
#define FEAT 256
#define MULC 64

typedef unsigned long long u64t;

// ---------------- scratch (static device globals; no allocs) ----------------
// QUAD layout: [node][u][4] = {x0[u], x1[u][0], x1[u][1], x1[u][2]}
__device__ float g_xl[N_NODES_MAX * FEAT];
__device__ float g_agg[N_NODES_MAX * FEAT];
// Stage-linearized weights for fctp_dual:
// iter i = v*64+u, stage s = i>>2, ui = i&3
// g_WSA[((s*4 + m)*4 + ui)*64 + w], m in {si0, si1, l10, l11}
__device__ float g_WSA[160 * 4 * 4 * 64];
// For fctp_final: stage s8 = i>>3, ui8 = i&7
// g_WSC[((s8*2 + m)*8 + ui8)*64 + w], m in {l20, l21}
__device__ float g_WSC[80 * 2 * 8 * 64];
// Lane-exact packed tp weights, de-interleaved
__device__ float g_tppA[32 * 32 * 4];
__device__ float g_tppB[32 * 32 * 4];

// ---------------- f32x2 packed-FMA helpers ----------------
__device__ __forceinline__ u64t pack2s(float a) {          // splat {a, a}
    u64t r;
    asm("mov.b64 %0, {%1, %1};" : "=l"(r) : "f"(a));
    return r;
}
__device__ __forceinline__ void unpack2(u64t v, float& a, float& b) {
    asm("mov.b64 {%0, %1}, %2;" : "=f"(a), "=f"(b) : "l"(v));
}
__device__ __forceinline__ void ffma2(u64t& d, u64t a, u64t b) {
    asm("fma.rn.f32x2 %0, %1, %2, %0;" : "+l"(d) : "l"(a), "l"(b));
}

__device__ __forceinline__ void red_add_v4(float* p, float4 v) {
    asm volatile("red.global.add.v4.f32 [%0], {%1,%2,%3,%4};"
                 :: "l"(p), "f"(v.x), "f"(v.y), "f"(v.z), "f"(v.w) : "memory");
}

// ---------------- cp.async helpers ----------------
__device__ __forceinline__ void cp16(uint32_t saddr, const float* g) {
    asm volatile("cp.async.cg.shared.global [%0], [%1], 16;" :: "r"(saddr), "l"(g));
}
__device__ __forceinline__ void cp_commit() {
    asm volatile("cp.async.commit_group;" ::: "memory");
}
__device__ __forceinline__ void cp_wait1() {
    asm volatile("cp.async.wait_group 1;" ::: "memory");
}

// ---------------- weight prepack ----------------
__global__ void prepack_kernel(const float* __restrict__ si0, const float* __restrict__ si1,
                               const float* __restrict__ l10, const float* __restrict__ l11,
                               const float* __restrict__ l20, const float* __restrict__ l21) {
    int idx = blockIdx.x * blockDim.x + threadIdx.x;  // idx = u*640 + v*64 + w
    if (idx >= 64 * 10 * 64) return;
    int w = idx & 63;
    int v = (idx >> 6) % 10;
    int u = idx / 640;
    int i = v * 64 + u;
    // dual staged layout (tile 4)
    int s = i >> 2, ui = i & 3;
    g_WSA[((s * 4 + 0) * 4 + ui) * 64 + w] = si0[idx];
    g_WSA[((s * 4 + 1) * 4 + ui) * 64 + w] = si1[idx];
    g_WSA[((s * 4 + 2) * 4 + ui) * 64 + w] = l10[idx];
    g_WSA[((s * 4 + 3) * 4 + ui) * 64 + w] = l11[idx];
    // final staged layout (tile 8)
    int s8 = i >> 3, ui8 = i & 7;
    g_WSC[((s8 * 2 + 0) * 8 + ui8) * 64 + w] = l20[idx];
    g_WSC[((s8 * 2 + 1) * 8 + ui8) * 64 + w] = l21[idx];
}

__global__ void prepack_tp_kernel(const float* __restrict__ tpw) {
    int i = blockIdx.x * blockDim.x + threadIdx.x;  // i = d*32 + lane
    if (i >= 32 * 32) return;
    int d = i >> 5, lane = i & 31;
    const float* row = tpw + d * 256;
    float* a = g_tppA + i * 4;
    a[0] = row[lane];        a[1] = row[64 + lane];
    a[2] = row[128 + lane];  a[3] = row[192 + lane];
    float* b = g_tppB + i * 4;
    b[0] = row[32 + lane];   b[1] = row[96 + lane];
    b[2] = row[160 + lane];  b[3] = row[224 + lane];
}

// ---------------- zero agg ----------------
__global__ void zero_agg_kernel(int n4) {
    float4* p = (float4*)g_agg;
    float4 z = make_float4(0.f, 0.f, 0.f, 0.f);
    for (int i = blockIdx.x * blockDim.x + threadIdx.x; i < n4; i += gridDim.x * blockDim.x)
        p[i] = z;
}

// ---------------- fctp dual: s -> out_s (orig layout), xl -> g_xl (quad layout) ----------------
// 160 stages x 4 u-iters; weights cp.async triple-buffered in smem.
__global__ __launch_bounds__(256) void fctp_dual_kernel(
    const float* __restrict__ x, const float* __restrict__ z,
    float* __restrict__ out_s, int n)
{
    __shared__ float4 Xs[64 * 32];               // 32 KB
    __shared__ __align__(16) float Wsm[3 * 1024]; // 12 KB triple buffer
    __shared__ float zsh[32][11];

    const int t = threadIdx.x;
    const int nbase = blockIdx.x * 32;
    const int ng = t >> 4;
    const int w4 = t & 15;
    const int ln0 = ng * 2;

    const uint32_t wbase = (uint32_t)__cvta_generic_to_shared(Wsm);

    // prologue: prefetch stages 0, 1 (1024 floats each = one 16B chunk per thread)
    cp16(wbase + t * 16, g_WSA + t * 4);
    cp_commit();
    cp16(wbase + 4096 + t * 16, g_WSA + 1024 + t * 4);
    cp_commit();

    // stage X and z (overlaps with cp.async)
#pragma unroll
    for (int i = 0; i < 8; i++) {
        int f = t + i * 256;
        int u = f >> 5, ln = f & 31;
        int node = nbase + ln;
        float4 val = make_float4(0.f, 0.f, 0.f, 0.f);
        if (node < n) {
            const float* xr = x + (size_t)node * FEAT;
            val.x = xr[u];
            val.y = xr[64 + 3 * u];
            val.z = xr[64 + 3 * u + 1];
            val.w = xr[64 + 3 * u + 2];
        }
        Xs[f] = val;
    }
    for (int i = t; i < 320; i += 256) {
        int ln = i / 10, v = i % 10;
        int node = nbase + ln;
        zsh[ln][v] = (node < n) ? z[(size_t)node * 10 + v] : 0.f;
    }
    __syncthreads();

    u64t accS2[16], accL2[16];
#pragma unroll
    for (int i = 0; i < 16; i++) { accS2[i] = 0ull; accL2[i] = 0ull; }

    int b = 0;   // buffer for current stage s
    for (int s = 0; s < 160; s++) {
        cp_wait1();
        __syncthreads();

        // prefetch stage s+2 into buffer (s+2)%3 (safe: all stage s-1 readers are past the sync)
        int s2 = s + 2;
        if (s2 < 160) {
            int b2 = b + 2; if (b2 >= 3) b2 -= 3;
            cp16(wbase + (b2 * 1024 + t * 4) * 4, g_WSA + (size_t)s2 * 1024 + t * 4);
        }
        cp_commit();

        const int v = s >> 4;
        const float zr0 = zsh[ln0][v];
        const float zr1 = zsh[ln0 + 1][v];
        const ulonglong2* Wb = (const ulonglong2*)(Wsm + b * 1024);
        const int ub = (s & 15) * 4;

#pragma unroll
        for (int ui = 0; ui < 4; ui++) {
            int u = ub + ui;
            float4 xq0 = Xs[u * 32 + ln0];
            float4 xq1 = Xs[u * 32 + ln0 + 1];
            ulonglong2 wsi0 = Wb[(0 * 4 + ui) * 16 + w4];
            ulonglong2 wsi1 = Wb[(1 * 4 + ui) * 16 + w4];
            ulonglong2 wl10 = Wb[(2 * 4 + ui) * 16 + w4];
            ulonglong2 wl11 = Wb[(3 * 4 + ui) * 16 + w4];

            u64t a00 = pack2s(xq0.x * zr0), a01 = pack2s(xq0.y * zr0);
            u64t a02 = pack2s(xq0.z * zr0), a03 = pack2s(xq0.w * zr0);
            u64t a10 = pack2s(xq1.x * zr1), a11 = pack2s(xq1.y * zr1);
            u64t a12 = pack2s(xq1.z * zr1), a13 = pack2s(xq1.w * zr1);

            ffma2(accS2[0],  a00, wsi0.x); ffma2(accS2[1],  a00, wsi0.y);
            ffma2(accS2[2],  a01, wsi1.x); ffma2(accS2[3],  a01, wsi1.y);
            ffma2(accS2[4],  a02, wsi1.x); ffma2(accS2[5],  a02, wsi1.y);
            ffma2(accS2[6],  a03, wsi1.x); ffma2(accS2[7],  a03, wsi1.y);
            ffma2(accS2[8],  a10, wsi0.x); ffma2(accS2[9],  a10, wsi0.y);
            ffma2(accS2[10], a11, wsi1.x); ffma2(accS2[11], a11, wsi1.y);
            ffma2(accS2[12], a12, wsi1.x); ffma2(accS2[13], a12, wsi1.y);
            ffma2(accS2[14], a13, wsi1.x); ffma2(accS2[15], a13, wsi1.y);

            ffma2(accL2[0],  a00, wl10.x); ffma2(accL2[1],  a00, wl10.y);
            ffma2(accL2[2],  a01, wl11.x); ffma2(accL2[3],  a01, wl11.y);
            ffma2(accL2[4],  a02, wl11.x); ffma2(accL2[5],  a02, wl11.y);
            ffma2(accL2[6],  a03, wl11.x); ffma2(accL2[7],  a03, wl11.y);
            ffma2(accL2[8],  a10, wl10.x); ffma2(accL2[9],  a10, wl10.y);
            ffma2(accL2[10], a11, wl11.x); ffma2(accL2[11], a11, wl11.y);
            ffma2(accL2[12], a12, wl11.x); ffma2(accL2[13], a12, wl11.y);
            ffma2(accL2[14], a13, wl11.x); ffma2(accL2[15], a13, wl11.y);
        }

        if (++b >= 3) b -= 3;
    }

    float accS[32], accL[32];
#pragma unroll
    for (int p = 0; p < 16; p++) {
        unpack2(accS2[p], accS[2 * p], accS[2 * p + 1]);
        unpack2(accL2[p], accL[2 * p], accL[2 * p + 1]);
    }

    const float sc = 0.03952847075210474f;  // 1/sqrt(640)
#pragma unroll
    for (int nn = 0; nn < 2; nn++) {
        int node = nbase + ln0 + nn;
        if (node >= n) continue;
        float* os = out_s + (size_t)node * FEAT;
        float4* ox4 = (float4*)(g_xl + (size_t)node * FEAT);
        const float* aS = accS + nn * 16;
        const float* aL = accL + nn * 16;
#pragma unroll
        for (int j = 0; j < 4; j++) {
            int w = w4 * 4 + j;
            os[w] = aS[j] * sc;
#pragma unroll
            for (int c = 1; c < 4; c++)
                os[64 + 3 * w + c - 1] = aS[c * 4 + j] * sc;
            ox4[w] = make_float4(aL[j] * sc, aL[4 + j] * sc, aL[8 + j] * sc, aL[12 + j] * sc);
        }
    }
}

// ---------------- final fctp: out += fctp(agg(quad), z, W_l2)/10 ----------------
// 80 stages x 8 u-iters; weights cp.async triple-buffered.
__global__ __launch_bounds__(256) void fctp_final_kernel(
    const float* __restrict__ z, float* __restrict__ out, int n)
{
    __shared__ float4 Xs[64 * 32];
    __shared__ __align__(16) float Wsm[3 * 1024];
    __shared__ float zsh[32][11];

    const int t = threadIdx.x;
    const int nbase = blockIdx.x * 32;
    const int ng = t >> 4;
    const int w4 = t & 15;
    const int ln0 = ng * 2;

    const uint32_t wbase = (uint32_t)__cvta_generic_to_shared(Wsm);

    cp16(wbase + t * 16, g_WSC + t * 4);
    cp_commit();
    cp16(wbase + 4096 + t * 16, g_WSC + 1024 + t * 4);
    cp_commit();

    const float4* agg4 = (const float4*)g_agg;
#pragma unroll
    for (int i = 0; i < 8; i++) {
        int f = t + i * 256;
        int u = f >> 5, ln = f & 31;
        int node = nbase + ln;
        Xs[f] = (node < n) ? agg4[(size_t)node * 64 + u]
                           : make_float4(0.f, 0.f, 0.f, 0.f);
    }
    for (int i = t; i < 320; i += 256) {
        int ln = i / 10, v = i % 10;
        int node = nbase + ln;
        zsh[ln][v] = (node < n) ? z[(size_t)node * 10 + v] : 0.f;
    }
    __syncthreads();

    u64t acc2[16];
#pragma unroll
    for (int i = 0; i < 16; i++) acc2[i] = 0ull;

    int b = 0;
    for (int s = 0; s < 80; s++) {
        cp_wait1();
        __syncthreads();

        int s2 = s + 2;
        if (s2 < 80) {
            int b2 = b + 2; if (b2 >= 3) b2 -= 3;
            cp16(wbase + (b2 * 1024 + t * 4) * 4, g_WSC + (size_t)s2 * 1024 + t * 4);
        }
        cp_commit();

        const int v = s >> 3;
        const float zr0 = zsh[ln0][v];
        const float zr1 = zsh[ln0 + 1][v];
        const ulonglong2* Wb = (const ulonglong2*)(Wsm + b * 1024);
        const int ub = (s & 7) * 8;

#pragma unroll
        for (int ui = 0; ui < 8; ui++) {
            int u = ub + ui;
            float4 xq0 = Xs[u * 32 + ln0];
            float4 xq1 = Xs[u * 32 + ln0 + 1];
            ulonglong2 wl20 = Wb[(0 * 8 + ui) * 16 + w4];
            ulonglong2 wl21 = Wb[(1 * 8 + ui) * 16 + w4];

            u64t a00 = pack2s(xq0.x * zr0), a01 = pack2s(xq0.y * zr0);
            u64t a02 = pack2s(xq0.z * zr0), a03 = pack2s(xq0.w * zr0);
            u64t a10 = pack2s(xq1.x * zr1), a11 = pack2s(xq1.y * zr1);
            u64t a12 = pack2s(xq1.z * zr1), a13 = pack2s(xq1.w * zr1);

            ffma2(acc2[0],  a00, wl20.x); ffma2(acc2[1],  a00, wl20.y);
            ffma2(acc2[2],  a01, wl21.x); ffma2(acc2[3],  a01, wl21.y);
            ffma2(acc2[4],  a02, wl21.x); ffma2(acc2[5],  a02, wl21.y);
            ffma2(acc2[6],  a03, wl21.x); ffma2(acc2[7],  a03, wl21.y);
            ffma2(acc2[8],  a10, wl20.x); ffma2(acc2[9],  a10, wl20.y);
            ffma2(acc2[10], a11, wl21.x); ffma2(acc2[11], a11, wl21.y);
            ffma2(acc2[12], a12, wl21.x); ffma2(acc2[13], a12, wl21.y);
            ffma2(acc2[14], a13, wl21.x); ffma2(acc2[15], a13, wl21.y);
        }

        if (++b >= 3) b -= 3;
    }

    float acc[32];
#pragma unroll
    for (int p = 0; p < 16; p++) unpack2(acc2[p], acc[2 * p], acc[2 * p + 1]);

    const float sc = 0.03952847075210474f * 0.1f;  // (1/sqrt(640)) / 10
#pragma unroll
    for (int nn = 0; nn < 2; nn++) {
        int node = nbase + ln0 + nn;
        if (node >= n) continue;
        float* os = out + (size_t)node * FEAT;
        const float* a = acc + nn * 16;
#pragma unroll
        for (int j = 0; j < 4; j++) {
            int w = w4 * 4 + j;
            os[w] += a[j] * sc;
#pragma unroll
            for (int c = 1; c < 4; c++)
                os[64 + 3 * w + c - 1] += a[c * 4 + j] * sc;
        }
    }
}

// ---------------- edge kernel: 4 edges/warp, no smem, f32x2 GEMM ----------------
#define EPW 4
__global__ __launch_bounds__(256) void edge_kernel(
    const int* __restrict__ esrc, const int* __restrict__ edst,
    const float* __restrict__ elen, const float* __restrict__ eattr,
    int n_edges)
{
    const int warp = threadIdx.x >> 5;
    const int lane = threadIdx.x & 31;
    const int ebase = (blockIdx.x * 8 + warp) * EPW;
    if (ebase >= n_edges) return;

    float el[EPW];
    int esafe[EPW];
    bool valid[EPW];
#pragma unroll
    for (int j = 0; j < EPW; j++) {
        int e = ebase + j;
        valid[j] = (e < n_edges);
        esafe[j] = valid[j] ? e : (n_edges - 1);
        el[j] = elen[(size_t)esafe[j] * 32 + lane];
    }

    u64t acc2[EPW * 4];
#pragma unroll
    for (int i = 0; i < EPW * 4; i++) acc2[i] = 0ull;
    const ulonglong2* tpA8 = (const ulonglong2*)g_tppA;
    const ulonglong2* tpB8 = (const ulonglong2*)g_tppB;
#pragma unroll 8
    for (int d = 0; d < 32; d++) {
        ulonglong2 tA = tpA8[d * 32 + lane];
        ulonglong2 tB = tpB8[d * 32 + lane];
#pragma unroll
        for (int j = 0; j < EPW; j++) {
            u64t ed = pack2s(__shfl_sync(0xffffffffu, el[j], d));
            ffma2(acc2[j * 4 + 0], ed, tA.x);
            ffma2(acc2[j * 4 + 1], ed, tA.y);
            ffma2(acc2[j * 4 + 2], ed, tB.x);
            ffma2(acc2[j * 4 + 3], ed, tB.y);
        }
    }

    const float ISQ2 = 0.7071067811865476f;
    const float ISQ3 = 0.5773502691896258f;

#pragma unroll
    for (int j = 0; j < EPW; j++) {
        if (!valid[j]) continue;
        int e = esafe[j];
        int src = esrc[e];
        int dst = edst[e];
        float4 at = ((const float4*)eattr)[e];  // (sh0, sh1x, sh1y, sh1z)

        float wv[8];
        unpack2(acc2[j * 4 + 0], wv[0], wv[1]);
        unpack2(acc2[j * 4 + 1], wv[2], wv[3]);
        unpack2(acc2[j * 4 + 2], wv[4], wv[5]);
        unpack2(acc2[j * 4 + 3], wv[6], wv[7]);

        const float4* xr = (const float4*)(g_xl + (size_t)src * FEAT);
        float* aggp = g_agg + (size_t)dst * FEAT;
#pragma unroll
        for (int h = 0; h < 2; h++) {
            float4 xq = xr[lane + 32 * h];     // {x0, x10, x11, x12}
            float w1  = wv[h * 4 + 0];
            float w2v = wv[h * 4 + 1];
            float w3  = wv[h * 4 + 2];
            float w4v = wv[h * 4 + 3];
            float dot = xq.y * at.y + xq.z * at.z + xq.w * at.w;
            float4 o;
            o.x = ISQ2 * (w1 * xq.x * at.x + ISQ3 * w4v * dot);
            o.y = ISQ2 * (w2v * xq.x * at.y + w3 * xq.y * at.x);
            o.z = ISQ2 * (w2v * xq.x * at.z + w3 * xq.z * at.x);
            o.w = ISQ2 * (w2v * xq.x * at.w + w3 * xq.w * at.x);
            red_add_v4(aggp + (lane + 32 * h) * 4, o);
        }
    }
}

// ---------------- launch ----------------
extern "C" void kernel_launch(void* const* d_in, const int* in_sizes, int n_in,
                              void* d_out, int out_size) {
    const float* x     = (const float*)d_in[0];
    const float* z     = (const float*)d_in[1];
    const int*   esrc  = (const int*)d_in[2];
    const int*   edst  = (const int*)d_in[3];
    const float* elen  = (const float*)d_in[4];
    const float* eattr = (const float*)d_in[5];
    const float* Wsi0  = (const float*)d_in[6];
    const float* Wsi1  = (const float*)d_in[7];
    const float* Wl10  = (const float*)d_in[8];
    const float* Wl11  = (const float*)d_in[9];
    const float* Wl20  = (const float*)d_in[10];
    const float* Wl21  = (const float*)d_in[11];
    const float* tpw   = (const float*)d_in[12];
    float* out = (float*)d_out;

    const int n_nodes = in_sizes[0] / FEAT;
    const int n_edges = in_sizes[2];

    prepack_kernel<<<(64 * 10 * 64 + 255) / 256, 256>>>(Wsi0, Wsi1, Wl10, Wl11, Wl20, Wl21);
    prepack_tp_kernel<<<4, 256>>>(tpw);
    zero_agg_kernel<<<512, 256>>>(n_nodes * (FEAT / 4));

    const int nblocks = (n_nodes + 31) / 32;
    fctp_dual_kernel<<<nblocks, 256>>>(x, z, out, n_nodes);

    const int edges_per_block = 8 * EPW;
    edge_kernel<<<(n_edges + edges_per_block - 1) / edges_per_block, 256>>>(
        esrc, edst, elen, eattr, n_edges);

    fctp_final_kernel<<<nblocks, 256>>>(z, out, n_nodes);
}

// round 8
// speedup vs baseline: 2.4425x; 1.1117x over previous
#include <cuda_runtime.h>
#include <cstdint>

#define N_NODES_MAX 50016
#define FEAT 256
#define MULC 64

typedef unsigned long long u64t;

// ---------------- scratch (static device globals; no allocs) ----------------
// QUAD layout: [node][u][4] = {x0[u], x1[u][0], x1[u][1], x1[u][2]}
__device__ float g_xl[N_NODES_MAX * FEAT];
__device__ float g_agg[N_NODES_MAX * FEAT];
// Stage-linearized weights for fctp_dual (stage = 8 u-iters):
// i = v*64+u, s = i>>3, ui = i&7 : g_WSA[((s*4 + m)*8 + ui)*64 + w]
__device__ float g_WSA[80 * 4 * 8 * 64];
// For fctp_final (stage = 16 u-iters): s16 = i>>4, ui = i&15
// g_WSC[((s16*2 + m)*16 + ui)*64 + w]
__device__ float g_WSC[40 * 2 * 16 * 64];
// Lane-exact packed tp weights, de-interleaved
__device__ float g_tppA[32 * 32 * 4];
__device__ float g_tppB[32 * 32 * 4];

// ---------------- f32x2 packed-FMA helpers ----------------
__device__ __forceinline__ u64t pack2s(float a) {          // splat {a, a}
    u64t r;
    asm("mov.b64 %0, {%1, %1};" : "=l"(r) : "f"(a));
    return r;
}
__device__ __forceinline__ void unpack2(u64t v, float& a, float& b) {
    asm("mov.b64 {%0, %1}, %2;" : "=f"(a), "=f"(b) : "l"(v));
}
__device__ __forceinline__ void ffma2(u64t& d, u64t a, u64t b) {
    asm("fma.rn.f32x2 %0, %1, %2, %0;" : "+l"(d) : "l"(a), "l"(b));
}

__device__ __forceinline__ void red_add_v4(float* p, float4 v) {
    asm volatile("red.global.add.v4.f32 [%0], {%1,%2,%3,%4};"
                 :: "l"(p), "f"(v.x), "f"(v.y), "f"(v.z), "f"(v.w) : "memory");
}

// ---------------- cp.async helpers ----------------
__device__ __forceinline__ void cp16(uint32_t saddr, const float* g) {
    asm volatile("cp.async.cg.shared.global [%0], [%1], 16;" :: "r"(saddr), "l"(g));
}
__device__ __forceinline__ void cp_commit() {
    asm volatile("cp.async.commit_group;" ::: "memory");
}
__device__ __forceinline__ void cp_wait1() {
    asm volatile("cp.async.wait_group 1;" ::: "memory");
}

#define STAGE_F 2048   // floats per stage (8 KB)

// ---------------- weight prepack ----------------
__global__ void prepack_kernel(const float* __restrict__ si0, const float* __restrict__ si1,
                               const float* __restrict__ l10, const float* __restrict__ l11,
                               const float* __restrict__ l20, const float* __restrict__ l21) {
    int idx = blockIdx.x * blockDim.x + threadIdx.x;  // idx = u*640 + v*64 + w
    if (idx >= 64 * 10 * 64) return;
    int w = idx & 63;
    int v = (idx >> 6) % 10;
    int u = idx / 640;
    int i = v * 64 + u;
    // dual staged layout (stage = 8 u-iters)
    int s = i >> 3, ui = i & 7;
    g_WSA[((s * 4 + 0) * 8 + ui) * 64 + w] = si0[idx];
    g_WSA[((s * 4 + 1) * 8 + ui) * 64 + w] = si1[idx];
    g_WSA[((s * 4 + 2) * 8 + ui) * 64 + w] = l10[idx];
    g_WSA[((s * 4 + 3) * 8 + ui) * 64 + w] = l11[idx];
    // final staged layout (stage = 16 u-iters)
    int s16 = i >> 4, ui16 = i & 15;
    g_WSC[((s16 * 2 + 0) * 16 + ui16) * 64 + w] = l20[idx];
    g_WSC[((s16 * 2 + 1) * 16 + ui16) * 64 + w] = l21[idx];
}

__global__ void prepack_tp_kernel(const float* __restrict__ tpw) {
    int i = blockIdx.x * blockDim.x + threadIdx.x;  // i = d*32 + lane
    if (i >= 32 * 32) return;
    int d = i >> 5, lane = i & 31;
    const float* row = tpw + d * 256;
    float* a = g_tppA + i * 4;
    a[0] = row[lane];        a[1] = row[64 + lane];
    a[2] = row[128 + lane];  a[3] = row[192 + lane];
    float* b = g_tppB + i * 4;
    b[0] = row[32 + lane];   b[1] = row[96 + lane];
    b[2] = row[160 + lane];  b[3] = row[224 + lane];
}

// ---------------- zero agg ----------------
__global__ void zero_agg_kernel(int n4) {
    float4* p = (float4*)g_agg;
    float4 z = make_float4(0.f, 0.f, 0.f, 0.f);
    for (int i = blockIdx.x * blockDim.x + threadIdx.x; i < n4; i += gridDim.x * blockDim.x)
        p[i] = z;
}

// ---------------- fctp dual: s -> out_s (orig layout), xl -> g_xl (quad layout) ----------------
// 80 stages x 8 u-iters; weights cp.async triple-buffered; 2 blocks/SM.
__global__ __launch_bounds__(256, 2) void fctp_dual_kernel(
    const float* __restrict__ x, const float* __restrict__ z,
    float* __restrict__ out_s, int n)
{
    __shared__ float4 Xs[64 * 32];                    // 32 KB
    __shared__ __align__(16) float Wsm[3 * STAGE_F];  // 24 KB triple buffer
    __shared__ float zsh[32][11];

    const int t = threadIdx.x;
    const int nbase = blockIdx.x * 32;
    const int ng = t >> 4;
    const int w4 = t & 15;
    const int ln0 = ng * 2;

    const uint32_t wbase = (uint32_t)__cvta_generic_to_shared(Wsm);

    // prologue: prefetch stages 0, 1 (2048 floats each = two 16B chunks per thread)
    cp16(wbase + t * 16, g_WSA + t * 4);
    cp16(wbase + 4096 + t * 16, g_WSA + 1024 + t * 4);
    cp_commit();
    cp16(wbase + 8192 + t * 16, g_WSA + 2048 + t * 4);
    cp16(wbase + 12288 + t * 16, g_WSA + 3072 + t * 4);
    cp_commit();

    // stage X and z (overlaps with cp.async)
#pragma unroll
    for (int i = 0; i < 8; i++) {
        int f = t + i * 256;
        int u = f >> 5, ln = f & 31;
        int node = nbase + ln;
        float4 val = make_float4(0.f, 0.f, 0.f, 0.f);
        if (node < n) {
            const float* xr = x + (size_t)node * FEAT;
            val.x = xr[u];
            val.y = xr[64 + 3 * u];
            val.z = xr[64 + 3 * u + 1];
            val.w = xr[64 + 3 * u + 2];
        }
        Xs[f] = val;
    }
    for (int i = t; i < 320; i += 256) {
        int ln = i / 10, v = i % 10;
        int node = nbase + ln;
        zsh[ln][v] = (node < n) ? z[(size_t)node * 10 + v] : 0.f;
    }
    __syncthreads();

    u64t accS2[16], accL2[16];
#pragma unroll
    for (int i = 0; i < 16; i++) { accS2[i] = 0ull; accL2[i] = 0ull; }

    int b = 0;   // buffer for current stage s
    for (int s = 0; s < 80; s++) {
        cp_wait1();
        __syncthreads();

        // prefetch stage s+2 into buffer (s+2)%3
        int s2 = s + 2;
        if (s2 < 80) {
            int b2 = b + 2; if (b2 >= 3) b2 -= 3;
            uint32_t sb = wbase + (b2 * STAGE_F + t * 4) * 4;
            const float* gb = g_WSA + (size_t)s2 * STAGE_F + t * 4;
            cp16(sb, gb);
            cp16(sb + 4096, gb + 1024);
        }
        cp_commit();

        const int v = s >> 3;
        const float zr0 = zsh[ln0][v];
        const float zr1 = zsh[ln0 + 1][v];
        const ulonglong2* Wb = (const ulonglong2*)(Wsm + b * STAGE_F);
        const int ub = (s & 7) * 8;

#pragma unroll
        for (int ui = 0; ui < 8; ui++) {
            int u = ub + ui;
            float4 xq0 = Xs[u * 32 + ln0];
            float4 xq1 = Xs[u * 32 + ln0 + 1];
            ulonglong2 wsi0 = Wb[(0 * 8 + ui) * 16 + w4];
            ulonglong2 wsi1 = Wb[(1 * 8 + ui) * 16 + w4];
            ulonglong2 wl10 = Wb[(2 * 8 + ui) * 16 + w4];
            ulonglong2 wl11 = Wb[(3 * 8 + ui) * 16 + w4];

            u64t a00 = pack2s(xq0.x * zr0), a01 = pack2s(xq0.y * zr0);
            u64t a02 = pack2s(xq0.z * zr0), a03 = pack2s(xq0.w * zr0);
            u64t a10 = pack2s(xq1.x * zr1), a11 = pack2s(xq1.y * zr1);
            u64t a12 = pack2s(xq1.z * zr1), a13 = pack2s(xq1.w * zr1);

            ffma2(accS2[0],  a00, wsi0.x); ffma2(accS2[1],  a00, wsi0.y);
            ffma2(accS2[2],  a01, wsi1.x); ffma2(accS2[3],  a01, wsi1.y);
            ffma2(accS2[4],  a02, wsi1.x); ffma2(accS2[5],  a02, wsi1.y);
            ffma2(accS2[6],  a03, wsi1.x); ffma2(accS2[7],  a03, wsi1.y);
            ffma2(accS2[8],  a10, wsi0.x); ffma2(accS2[9],  a10, wsi0.y);
            ffma2(accS2[10], a11, wsi1.x); ffma2(accS2[11], a11, wsi1.y);
            ffma2(accS2[12], a12, wsi1.x); ffma2(accS2[13], a12, wsi1.y);
            ffma2(accS2[14], a13, wsi1.x); ffma2(accS2[15], a13, wsi1.y);

            ffma2(accL2[0],  a00, wl10.x); ffma2(accL2[1],  a00, wl10.y);
            ffma2(accL2[2],  a01, wl11.x); ffma2(accL2[3],  a01, wl11.y);
            ffma2(accL2[4],  a02, wl11.x); ffma2(accL2[5],  a02, wl11.y);
            ffma2(accL2[6],  a03, wl11.x); ffma2(accL2[7],  a03, wl11.y);
            ffma2(accL2[8],  a10, wl10.x); ffma2(accL2[9],  a10, wl10.y);
            ffma2(accL2[10], a11, wl11.x); ffma2(accL2[11], a11, wl11.y);
            ffma2(accL2[12], a12, wl11.x); ffma2(accL2[13], a12, wl11.y);
            ffma2(accL2[14], a13, wl11.x); ffma2(accL2[15], a13, wl11.y);
        }

        if (++b >= 3) b -= 3;
    }

    float accS[32], accL[32];
#pragma unroll
    for (int p = 0; p < 16; p++) {
        unpack2(accS2[p], accS[2 * p], accS[2 * p + 1]);
        unpack2(accL2[p], accL[2 * p], accL[2 * p + 1]);
    }

    const float sc = 0.03952847075210474f;  // 1/sqrt(640)
#pragma unroll
    for (int nn = 0; nn < 2; nn++) {
        int node = nbase + ln0 + nn;
        if (node >= n) continue;
        float* os = out_s + (size_t)node * FEAT;
        float4* ox4 = (float4*)(g_xl + (size_t)node * FEAT);
        const float* aS = accS + nn * 16;
        const float* aL = accL + nn * 16;
#pragma unroll
        for (int j = 0; j < 4; j++) {
            int w = w4 * 4 + j;
            os[w] = aS[j] * sc;
#pragma unroll
            for (int c = 1; c < 4; c++)
                os[64 + 3 * w + c - 1] = aS[c * 4 + j] * sc;
            ox4[w] = make_float4(aL[j] * sc, aL[4 + j] * sc, aL[8 + j] * sc, aL[12 + j] * sc);
        }
    }
}

// ---------------- final fctp: out += fctp(agg(quad), z, W_l2)/10 ----------------
// 40 stages x 16 u-iters; weights cp.async triple-buffered; 2 blocks/SM.
__global__ __launch_bounds__(256, 2) void fctp_final_kernel(
    const float* __restrict__ z, float* __restrict__ out, int n)
{
    __shared__ float4 Xs[64 * 32];
    __shared__ __align__(16) float Wsm[3 * STAGE_F];
    __shared__ float zsh[32][11];

    const int t = threadIdx.x;
    const int nbase = blockIdx.x * 32;
    const int ng = t >> 4;
    const int w4 = t & 15;
    const int ln0 = ng * 2;

    const uint32_t wbase = (uint32_t)__cvta_generic_to_shared(Wsm);

    cp16(wbase + t * 16, g_WSC + t * 4);
    cp16(wbase + 4096 + t * 16, g_WSC + 1024 + t * 4);
    cp_commit();
    cp16(wbase + 8192 + t * 16, g_WSC + 2048 + t * 4);
    cp16(wbase + 12288 + t * 16, g_WSC + 3072 + t * 4);
    cp_commit();

    const float4* agg4 = (const float4*)g_agg;
#pragma unroll
    for (int i = 0; i < 8; i++) {
        int f = t + i * 256;
        int u = f >> 5, ln = f & 31;
        int node = nbase + ln;
        Xs[f] = (node < n) ? agg4[(size_t)node * 64 + u]
                           : make_float4(0.f, 0.f, 0.f, 0.f);
    }
    for (int i = t; i < 320; i += 256) {
        int ln = i / 10, v = i % 10;
        int node = nbase + ln;
        zsh[ln][v] = (node < n) ? z[(size_t)node * 10 + v] : 0.f;
    }
    __syncthreads();

    u64t acc2[16];
#pragma unroll
    for (int i = 0; i < 16; i++) acc2[i] = 0ull;

    int b = 0;
    for (int s = 0; s < 40; s++) {
        cp_wait1();
        __syncthreads();

        int s2 = s + 2;
        if (s2 < 40) {
            int b2 = b + 2; if (b2 >= 3) b2 -= 3;
            uint32_t sb = wbase + (b2 * STAGE_F + t * 4) * 4;
            const float* gb = g_WSC + (size_t)s2 * STAGE_F + t * 4;
            cp16(sb, gb);
            cp16(sb + 4096, gb + 1024);
        }
        cp_commit();

        const int v = s >> 2;
        const float zr0 = zsh[ln0][v];
        const float zr1 = zsh[ln0 + 1][v];
        const ulonglong2* Wb = (const ulonglong2*)(Wsm + b * STAGE_F);
        const int ub = (s & 3) * 16;

#pragma unroll
        for (int ui = 0; ui < 16; ui++) {
            int u = ub + ui;
            float4 xq0 = Xs[u * 32 + ln0];
            float4 xq1 = Xs[u * 32 + ln0 + 1];
            ulonglong2 wl20 = Wb[(0 * 16 + ui) * 16 + w4];
            ulonglong2 wl21 = Wb[(1 * 16 + ui) * 16 + w4];

            u64t a00 = pack2s(xq0.x * zr0), a01 = pack2s(xq0.y * zr0);
            u64t a02 = pack2s(xq0.z * zr0), a03 = pack2s(xq0.w * zr0);
            u64t a10 = pack2s(xq1.x * zr1), a11 = pack2s(xq1.y * zr1);
            u64t a12 = pack2s(xq1.z * zr1), a13 = pack2s(xq1.w * zr1);

            ffma2(acc2[0],  a00, wl20.x); ffma2(acc2[1],  a00, wl20.y);
            ffma2(acc2[2],  a01, wl21.x); ffma2(acc2[3],  a01, wl21.y);
            ffma2(acc2[4],  a02, wl21.x); ffma2(acc2[5],  a02, wl21.y);
            ffma2(acc2[6],  a03, wl21.x); ffma2(acc2[7],  a03, wl21.y);
            ffma2(acc2[8],  a10, wl20.x); ffma2(acc2[9],  a10, wl20.y);
            ffma2(acc2[10], a11, wl21.x); ffma2(acc2[11], a11, wl21.y);
            ffma2(acc2[12], a12, wl21.x); ffma2(acc2[13], a12, wl21.y);
            ffma2(acc2[14], a13, wl21.x); ffma2(acc2[15], a13, wl21.y);
        }

        if (++b >= 3) b -= 3;
    }

    float acc[32];
#pragma unroll
    for (int p = 0; p < 16; p++) unpack2(acc2[p], acc[2 * p], acc[2 * p + 1]);

    const float sc = 0.03952847075210474f * 0.1f;  // (1/sqrt(640)) / 10
#pragma unroll
    for (int nn = 0; nn < 2; nn++) {
        int node = nbase + ln0 + nn;
        if (node >= n) continue;
        float* os = out + (size_t)node * FEAT;
        const float* a = acc + nn * 16;
#pragma unroll
        for (int j = 0; j < 4; j++) {
            int w = w4 * 4 + j;
            os[w] += a[j] * sc;
#pragma unroll
            for (int c = 1; c < 4; c++)
                os[64 + 3 * w + c - 1] += a[c * 4 + j] * sc;
        }
    }
}

// ---------------- edge kernel: 4 edges/warp, no smem, f32x2 GEMM ----------------
#define EPW 4
__global__ __launch_bounds__(256) void edge_kernel(
    const int* __restrict__ esrc, const int* __restrict__ edst,
    const float* __restrict__ elen, const float* __restrict__ eattr,
    int n_edges)
{
    const int warp = threadIdx.x >> 5;
    const int lane = threadIdx.x & 31;
    const int ebase = (blockIdx.x * 8 + warp) * EPW;
    if (ebase >= n_edges) return;

    float el[EPW];
    int esafe[EPW];
    bool valid[EPW];
#pragma unroll
    for (int j = 0; j < EPW; j++) {
        int e = ebase + j;
        valid[j] = (e < n_edges);
        esafe[j] = valid[j] ? e : (n_edges - 1);
        el[j] = elen[(size_t)esafe[j] * 32 + lane];
    }

    u64t acc2[EPW * 4];
#pragma unroll
    for (int i = 0; i < EPW * 4; i++) acc2[i] = 0ull;
    const ulonglong2* tpA8 = (const ulonglong2*)g_tppA;
    const ulonglong2* tpB8 = (const ulonglong2*)g_tppB;
#pragma unroll 8
    for (int d = 0; d < 32; d++) {
        ulonglong2 tA = tpA8[d * 32 + lane];
        ulonglong2 tB = tpB8[d * 32 + lane];
#pragma unroll
        for (int j = 0; j < EPW; j++) {
            u64t ed = pack2s(__shfl_sync(0xffffffffu, el[j], d));
            ffma2(acc2[j * 4 + 0], ed, tA.x);
            ffma2(acc2[j * 4 + 1], ed, tA.y);
            ffma2(acc2[j * 4 + 2], ed, tB.x);
            ffma2(acc2[j * 4 + 3], ed, tB.y);
        }
    }

    const float ISQ2 = 0.7071067811865476f;
    const float ISQ3 = 0.5773502691896258f;

#pragma unroll
    for (int j = 0; j < EPW; j++) {
        if (!valid[j]) continue;
        int e = esafe[j];
        int src = esrc[e];
        int dst = edst[e];
        float4 at = ((const float4*)eattr)[e];  // (sh0, sh1x, sh1y, sh1z)

        float wv[8];
        unpack2(acc2[j * 4 + 0], wv[0], wv[1]);
        unpack2(acc2[j * 4 + 1], wv[2], wv[3]);
        unpack2(acc2[j * 4 + 2], wv[4], wv[5]);
        unpack2(acc2[j * 4 + 3], wv[6], wv[7]);

        const float4* xr = (const float4*)(g_xl + (size_t)src * FEAT);
        float* aggp = g_agg + (size_t)dst * FEAT;
#pragma unroll
        for (int h = 0; h < 2; h++) {
            float4 xq = xr[lane + 32 * h];     // {x0, x10, x11, x12}
            float w1  = wv[h * 4 + 0];
            float w2v = wv[h * 4 + 1];
            float w3  = wv[h * 4 + 2];
            float w4v = wv[h * 4 + 3];
            float dot = xq.y * at.y + xq.z * at.z + xq.w * at.w;
            float4 o;
            o.x = ISQ2 * (w1 * xq.x * at.x + ISQ3 * w4v * dot);
            o.y = ISQ2 * (w2v * xq.x * at.y + w3 * xq.y * at.x);
            o.z = ISQ2 * (w2v * xq.x * at.z + w3 * xq.z * at.x);
            o.w = ISQ2 * (w2v * xq.x * at.w + w3 * xq.w * at.x);
            red_add_v4(aggp + (lane + 32 * h) * 4, o);
        }
    }
}

// ---------------- launch ----------------
extern "C" void kernel_launch(void* const* d_in, const int* in_sizes, int n_in,
                              void* d_out, int out_size) {
    const float* x     = (const float*)d_in[0];
    const float* z     = (const float*)d_in[1];
    const int*   esrc  = (const int*)d_in[2];
    const int*   edst  = (const int*)d_in[3];
    const float* elen  = (const float*)d_in[4];
    const float* eattr = (const float*)d_in[5];
    const float* Wsi0  = (const float*)d_in[6];
    const float* Wsi1  = (const float*)d_in[7];
    const float* Wl10  = (const float*)d_in[8];
    const float* Wl11  = (const float*)d_in[9];
    const float* Wl20  = (const float*)d_in[10];
    const float* Wl21  = (const float*)d_in[11];
    const float* tpw   = (const float*)d_in[12];
    float* out = (float*)d_out;

    const int n_nodes = in_sizes[0] / FEAT;
    const int n_edges = in_sizes[2];

    prepack_kernel<<<(64 * 10 * 64 + 255) / 256, 256>>>(Wsi0, Wsi1, Wl10, Wl11, Wl20, Wl21);
    prepack_tp_kernel<<<4, 256>>>(tpw);
    zero_agg_kernel<<<512, 256>>>(n_nodes * (FEAT / 4));

    const int nblocks = (n_nodes + 31) / 32;
    fctp_dual_kernel<<<nblocks, 256>>>(x, z, out, n_nodes);

    const int edges_per_block = 8 * EPW;
    edge_kernel<<<(n_edges + edges_per_block - 1) / edges_per_block, 256>>>(
        esrc, edst, elen, eattr, n_edges);

    fctp_final_kernel<<<nblocks, 256>>>(z, out, n_nodes);
}